// round 13
// baseline (speedup 1.0000x reference)
#include <cuda_runtime.h>
#include <cuda_bf16.h>
#include <cstdint>
#include <cfloat>
#include <math.h>

#define NPTS 12000
#define MPAD 12032
#define HID  256
#define KNB  16
#define G    64
#define NCELL (G * G)

// ---------------- scratch (allocation-free: __device__ globals) --------------
__device__ float g_h   [MPAD * HID];
__device__ int   g_nidx[NPTS * KNB];
__device__ float g_nw  [NPTS * KNB];

__device__ __nv_bfloat16 g_ah[MPAD * HID], g_al[MPAD * HID];   // h split
__device__ __nv_bfloat16 g_gh[MPAD * HID], g_gl[MPAD * HID];   // agg split
#define WTOT 360448
#define WENC 65536
__device__ __nv_bfloat16 g_wh[WTOT], g_wl[WTOT];
// slots: enc=0, g1ws=65536, g1wn=131072, g2ws=196608, g2wn=262144, cls=327680

// grid-knn scratch
__device__ unsigned int g_bbox[4];
__device__ int    g_cellstart[NCELL + 1];
__device__ float2 g_pts [NPTS];
__device__ int    g_sidx[NPTS];

__device__ __forceinline__ float gelu_f(float x) {
    return 0.5f * x * (1.0f + erff(x * 0.70710678118654752440f));
}

__device__ __forceinline__ unsigned int fenc(float f) {
    unsigned int u = __float_as_uint(f);
    return (u & 0x80000000u) ? ~u : (u | 0x80000000u);
}
__device__ __forceinline__ float fdec(unsigned int u) {
    return __uint_as_float((u & 0x80000000u) ? (u ^ 0x80000000u) : ~u);
}

__device__ __forceinline__ uint32_t smem_u32(const void* p) {
    uint32_t a;
    asm("{ .reg .u64 t; cvta.to.shared.u64 t, %1; cvt.u32.u64 %0, t; }" : "=r"(a) : "l"(p));
    return a;
}
__device__ __forceinline__ void cpa16(__nv_bfloat16* dst, const __nv_bfloat16* src) {
    const uint32_t d = smem_u32(dst);
    asm volatile("cp.async.cg.shared.global [%0], [%1], 16;" :: "r"(d), "l"(src) : "memory");
}
__device__ __forceinline__ void ldsm_x4(uint32_t* r, uint32_t addr) {
    asm volatile("ldmatrix.sync.aligned.m8n8.x4.shared.b16 {%0,%1,%2,%3}, [%4];"
                 : "=r"(r[0]), "=r"(r[1]), "=r"(r[2]), "=r"(r[3]) : "r"(addr));
}

// HMMA: D(f32) += A(bf16,row) * B(bf16,col), m16n8k16
__device__ __forceinline__ void mma16816(float* c, const uint32_t* a, const uint32_t* b) {
    asm volatile(
        "mma.sync.aligned.m16n8k16.row.col.f32.bf16.bf16.f32 "
        "{%0,%1,%2,%3}, {%4,%5,%6,%7}, {%8,%9}, {%0,%1,%2,%3};"
        : "+f"(c[0]), "+f"(c[1]), "+f"(c[2]), "+f"(c[3])
        : "r"(a[0]), "r"(a[1]), "r"(a[2]), "r"(a[3]), "r"(b[0]), "r"(b[1]));
}

// ================= KNN build: ONE CTA does bbox+count+scan+scatter =============
__global__ __launch_bounds__(1024) void knn_build_kernel(const float* __restrict__ cents) {
    __shared__ int   scnt[NCELL];
    __shared__ float rmnx[32], rmxx[32], rmny[32], rmxy[32];
    __shared__ float sbb[4];
    __shared__ int   wsum[32];
    const int t = threadIdx.x;
    const int lane = t & 31;
    const int warp = t >> 5;

    float2 pts[12];
    int np = 0;
    for (int i = t; i < NPTS; i += 1024) pts[np++] = *reinterpret_cast<const float2*>(cents + 2 * i);

    float xmn = FLT_MAX, xmx = -FLT_MAX, ymn = FLT_MAX, ymx = -FLT_MAX;
    for (int j = 0; j < np; ++j) {
        xmn = fminf(xmn, pts[j].x); xmx = fmaxf(xmx, pts[j].x);
        ymn = fminf(ymn, pts[j].y); ymx = fmaxf(ymx, pts[j].y);
    }
#pragma unroll
    for (int o = 16; o > 0; o >>= 1) {
        xmn = fminf(xmn, __shfl_xor_sync(0xffffffffu, xmn, o));
        xmx = fmaxf(xmx, __shfl_xor_sync(0xffffffffu, xmx, o));
        ymn = fminf(ymn, __shfl_xor_sync(0xffffffffu, ymn, o));
        ymx = fmaxf(ymx, __shfl_xor_sync(0xffffffffu, ymx, o));
    }
    if (lane == 0) { rmnx[warp] = xmn; rmxx[warp] = xmx; rmny[warp] = ymn; rmxy[warp] = ymx; }
    __syncthreads();
    if (t == 0) {
        float a = rmnx[0], b = rmxx[0], c = rmny[0], d = rmxy[0];
        for (int i = 1; i < 32; ++i) {
            a = fminf(a, rmnx[i]); b = fmaxf(b, rmxx[i]);
            c = fminf(c, rmny[i]); d = fmaxf(d, rmxy[i]);
        }
        sbb[0] = a; sbb[1] = b; sbb[2] = c; sbb[3] = d;
        g_bbox[0] = fenc(a); g_bbox[1] = fenc(b);
        g_bbox[2] = fenc(c); g_bbox[3] = fenc(d);
    }
    for (int c = t; c < NCELL; c += 1024) scnt[c] = 0;
    __syncthreads();

    const float xmin = sbb[0], ymin = sbb[2];
    const float rx = fmaxf(sbb[1] - xmin, 1e-20f);
    const float ry = fmaxf(sbb[3] - ymin, 1e-20f);
    const float iwx = (float)G / rx, iwy = (float)G / ry;

    int cellid[12];
    for (int j = 0; j < np; ++j) {
        int cx = (int)((pts[j].x - xmin) * iwx); cx = min(max(cx, 0), G - 1);
        int cy = (int)((pts[j].y - ymin) * iwy); cy = min(max(cy, 0), G - 1);
        cellid[j] = cy * G + cx;
        atomicAdd(&scnt[cellid[j]], 1);
    }
    __syncthreads();

    const int base = t * 4;
    int loc[4];
    int s = 0;
#pragma unroll
    for (int j = 0; j < 4; ++j) { loc[j] = s; s += scnt[base + j]; }
    int v = s;
#pragma unroll
    for (int o = 1; o < 32; o <<= 1) {
        const int n = __shfl_up_sync(0xffffffffu, v, o);
        if (lane >= o) v += n;
    }
    if (lane == 31) wsum[warp] = v;
    __syncthreads();
    if (t == 0) {
        int run = 0;
        for (int i = 0; i < 32; ++i) { const int tmp = wsum[i]; wsum[i] = run; run += tmp; }
    }
    __syncthreads();
    const int pre = wsum[warp] + (v - s);
#pragma unroll
    for (int j = 0; j < 4; ++j) loc[j] += pre;
#pragma unroll
    for (int j = 0; j < 4; ++j) g_cellstart[base + j] = loc[j];
    if (t == 1023) g_cellstart[NCELL] = NPTS;
    __syncthreads();
#pragma unroll
    for (int j = 0; j < 4; ++j) scnt[base + j] = loc[j];
    __syncthreads();

    for (int j = 0; j < np; ++j) {
        const int slot = atomicAdd(&scnt[cellid[j]], 1);
        g_pts [slot] = pts[j];
        g_sidx[slot] = t + 1024 * j;
    }
}

__device__ __forceinline__ void grid_params(float& xmin, float& ymin,
                                            float& iwx, float& iwy,
                                            float& wx, float& wy) {
    xmin = fdec(g_bbox[0]);
    const float xmax = fdec(g_bbox[1]);
    ymin = fdec(g_bbox[2]);
    const float ymax = fdec(g_bbox[3]);
    const float rx = fmaxf(xmax - xmin, 1e-20f);
    const float ry = fmaxf(ymax - ymin, 1e-20f);
    iwx = (float)G / rx; iwy = (float)G / ry;
    wx = rx / (float)G;  wy = ry / (float)G;
}

__device__ __forceinline__ int cell_x(float x, float xmin, float iwx) {
    int c = (int)((x - xmin) * iwx);
    return min(max(c, 0), G - 1);
}

// ================= KNN query: warp/query, PER-LANE top-16, warp merge =========
// Lane-local acceptance (no ballot serialization). Exact: every global top-16
// candidate lies in its lane's local top-16; termination uses
// U = warp_min(lane 16th best) >= global d16 (conservative).
__global__ void knn_query_kernel(int* __restrict__ nidx, float* __restrict__ nw) {
    const int w = (blockIdx.x * blockDim.x + threadIdx.x) >> 5;
    const int lane = threadIdx.x & 31;
    if (w >= NPTS) return;
    const int s = w;
    const float2 q = g_pts[s];
    const int i = g_sidx[s];

    float xmin, ymin, iwx, iwy, wx, wy;
    grid_params(xmin, ymin, iwx, iwy, wx, wy);
    const int cx = cell_x(q.x, xmin, iwx);
    const int cy = cell_x(q.y, ymin, iwy);

    float vals[KNB];
    int   ids [KNB];
#pragma unroll
    for (int t = 0; t < KNB; ++t) { vals[t] = FLT_MAX; ids[t] = 0; }
    float maxv = FLT_MAX;   // lane-local 16th best
    int   maxslot = 0;

    for (int r = 0; r < G; ++r) {
        const int ylo = max(cy - r, 0), yhi = min(cy + r, G - 1);
        for (int vy = ylo; vy <= yhi; ++vy) {
            const bool edge_row = (vy == cy - r) || (vy == cy + r);
            int ps0 = 0, pe0 = 0, ps1 = 0, pe1 = 0;
            if (edge_row) {
                const int xl = max(cx - r, 0), xh = min(cx + r, G - 1);
                ps0 = g_cellstart[vy * G + xl];
                pe0 = g_cellstart[vy * G + xh + 1];
            } else {
                if (cx - r >= 0) {
                    ps0 = g_cellstart[vy * G + cx - r];
                    pe0 = g_cellstart[vy * G + cx - r + 1];
                }
                if (cx + r <= G - 1) {
                    ps1 = g_cellstart[vy * G + cx + r];
                    pe1 = g_cellstart[vy * G + cx + r + 1];
                }
            }
#pragma unroll
            for (int seg = 0; seg < 2; ++seg) {
                const int ps = seg ? ps1 : ps0;
                const int pe = seg ? pe1 : pe0;
                for (int p0 = ps; p0 < pe; p0 += 32) {
                    const int p = p0 + lane;
                    if (p < pe && p != s) {
                        const float2 f = g_pts[p];
                        const float dx = q.x - f.x;
                        const float dy = q.y - f.y;
                        const float d2 = fmaf(dx, dx, dy * dy);
                        if (d2 < maxv) {      // lane-local insert, no warp traffic
#pragma unroll
                            for (int t = 0; t < KNB; ++t)
                                if (t == maxslot) { vals[t] = d2; ids[t] = p; }
                            maxv = vals[0]; maxslot = 0;
#pragma unroll
                            for (int t = 1; t < KNB; ++t)
                                if (vals[t] > maxv) { maxv = vals[t]; maxslot = t; }
                        }
                    }
                }
            }
        }
        // exact conservative termination: U >= global 16th best
        float U = maxv;
#pragma unroll
        for (int o = 16; o > 0; o >>= 1)
            U = fminf(U, __shfl_xor_sync(0xffffffffu, U, o));
        const float bl = (cx - r > 0)     ? q.x - (xmin + (float)(cx - r) * wx)     : FLT_MAX;
        const float br = (cx + r < G - 1) ? (xmin + (float)(cx + r + 1) * wx) - q.x : FLT_MAX;
        const float bb = (cy - r > 0)     ? q.y - (ymin + (float)(cy - r) * wy)     : FLT_MAX;
        const float bt = (cy + r < G - 1) ? (ymin + (float)(cy + r + 1) * wy) - q.y : FLT_MAX;
        const float b = fminf(fminf(bl, br), fminf(bb, bt));
        if (b == FLT_MAX || (b > 0.0f && b * b > U)) break;
    }

    // warp merge: 16 rounds of pop-min over 32x16 u64 keys (mono(d2)<<32 | slot)
    unsigned long long keys[KNB];
#pragma unroll
    for (int t = 0; t < KNB; ++t)
        keys[t] = ((unsigned long long)fenc(vals[t]) << 32) | (unsigned int)ids[t];

    unsigned long long sel = ~0ull;
    for (int round = 0; round < KNB; ++round) {
        unsigned long long m = keys[0]; int ms = 0;
#pragma unroll
        for (int t = 1; t < KNB; ++t)
            if (keys[t] < m) { m = keys[t]; ms = t; }
        unsigned long long g = m;
#pragma unroll
        for (int o = 16; o > 0; o >>= 1) {
            const unsigned long long t = __shfl_xor_sync(0xffffffffu, g, o);
            if (t < g) g = t;
        }
        if (m == g) {
#pragma unroll
            for (int t = 0; t < KNB; ++t)
                if (t == ms) keys[t] = ~0ull;
        }
        if (lane == round) sel = g;
    }

    // lanes 0..15 rescore winners with the reference's exact formula/rounding
    float invd = 0.0f;
    int oid = 0;
    if (lane < KNB) {
        const int p = (int)(sel & 0xffffffffu);
        const float2 f = g_pts[p];
        oid = g_sidx[p];
        const float xi = q.x, yi = q.y;
        const float sqi = __fadd_rn(__fmul_rn(xi, xi), __fmul_rn(yi, yi));
        const float sqj = __fadd_rn(__fmul_rn(f.x, f.x), __fmul_rn(f.y, f.y));
        const float dot = __fadd_rn(__fmul_rn(xi, f.x), __fmul_rn(yi, f.y));
        const float d2  = __fsub_rn(__fadd_rn(sqi, sqj), __fmul_rn(2.0f, dot));
        const float dist = sqrtf(fmaxf(d2, 0.0f));
        invd = 1.0f / fmaxf(dist, 1e-4f);
    }
    float tot = invd;
#pragma unroll
    for (int o = 16; o > 0; o >>= 1)
        tot += __shfl_xor_sync(0xffffffffu, tot, o);
    if (lane < KNB) {
        nidx[i * KNB + lane] = oid;
        nw  [i * KNB + lane] = invd / fmaxf(tot, 1e-8f);
    }
}

// ================= weight split (ranged) =======================================
__global__ void split_w_kernel(const float* __restrict__ w0, const float* __restrict__ w1,
                               const float* __restrict__ w2, const float* __restrict__ w3,
                               const float* __restrict__ w4, const float* __restrict__ w5,
                               int lo, int hi) {
    const int i = lo + blockIdx.x * blockDim.x + threadIdx.x;
    if (i >= hi) return;
    float x;
    if      (i < 65536)  x = w0[i];
    else if (i < 131072) x = w1[i - 65536];
    else if (i < 196608) x = w2[i - 131072];
    else if (i < 262144) x = w3[i - 196608];
    else if (i < 327680) x = w4[i - 262144];
    else                 x = w5[i - 327680];
    const __nv_bfloat16 h = __float2bfloat16(x);
    g_wh[i] = h;
    g_wl[i] = __float2bfloat16(x - __bfloat162float(h));
}

// ================= HMMA GEMM: fused epilogues ==================================
#define SPAD 40
template <int NCOLS, int MODE, bool DUAL, bool CONVA>
__global__ __launch_bounds__(256, 2) void hmma_gemm_kernel(
    const __nv_bfloat16* __restrict__ a1h, const __nv_bfloat16* __restrict__ a1l,
    const float* __restrict__ a1f,
    const __nv_bfloat16* __restrict__ w1h, const __nv_bfloat16* __restrict__ w1l,
    const __nv_bfloat16* __restrict__ a2h, const __nv_bfloat16* __restrict__ a2l,
    const __nv_bfloat16* __restrict__ w2h, const __nv_bfloat16* __restrict__ w2l,
    const float* __restrict__ bias,
    const float* __restrict__ gamma, const float* __restrict__ beta,
    const float* __restrict__ cw2, const float* __restrict__ cb2,
    float* __restrict__ outS,
    float* outF,
    __nv_bfloat16* __restrict__ outH, __nv_bfloat16* __restrict__ outL, int M) {
    extern __shared__ __nv_bfloat16 smem[];
    __shared__ float red[64][4][2];

    constexpr int SA = 64 * SPAD;
    constexpr int SB = NCOLS * SPAD;
    constexpr int SST = 2 * SA + 2 * SB;
    constexpr int NJ = NCOLS / 32;
    constexpr int NJP = NJ / 2;

    const int tid  = threadIdx.x;
    const int wid  = tid >> 5;
    const int lane = tid & 31;
    const int gid  = lane >> 2;
    const int tig  = lane & 3;
    const int m0 = blockIdx.x * 64;
    const int mw = (wid >> 2) * 32;
    const int nw = (wid & 3) * (NCOLS / 4);
    const int nchunks = DUAL ? 16 : 8;

    const uint32_t aLane = (uint32_t)(((mw + (lane & 15)) * SPAD + ((lane >> 4) & 1) * 8) * 2);
    const uint32_t bLane = (uint32_t)(((nw + 8 * ((lane >> 4) & 1) + (lane & 7)) * SPAD +
                                       ((lane >> 3) & 1) * 8) * 2);

    float acc[2][NJ][4];
#pragma unroll
    for (int a = 0; a < 2; ++a)
#pragma unroll
        for (int b = 0; b < NJ; ++b)
#pragma unroll
            for (int c = 0; c < 4; ++c) acc[a][b][c] = 0.0f;

    auto stage = [&](int c) {
        const int k0 = (c & 7) * 32;
        const bool s1 = DUAL && (c >= 8);
        const __nv_bfloat16* Ah = s1 ? a2h : a1h;
        const __nv_bfloat16* Al = s1 ? a2l : a1l;
        const __nv_bfloat16* Wh = s1 ? w2h : w1h;
        const __nv_bfloat16* Wl = s1 ? w2l : w1l;
        __nv_bfloat16* buf = smem + (c & 1) * SST;
        __nv_bfloat16* bAh = buf;
        __nv_bfloat16* bAl = buf + SA;
        __nv_bfloat16* bBh = buf + 2 * SA;
        __nv_bfloat16* bBl = buf + 2 * SA + SB;
        {
            const int r = tid >> 2, qd = tid & 3;
            const int off = r * SPAD + qd * 8;
            if (CONVA) {
                const int mg = m0 + r;
                __align__(16) __nv_bfloat16 hh[8], ll[8];
                if (mg < M) {
                    const float* fp = a1f + (size_t)mg * HID + k0 + qd * 8;
                    const float4 f0 = *reinterpret_cast<const float4*>(fp);
                    const float4 f1 = *reinterpret_cast<const float4*>(fp + 4);
                    const float fv[8] = {f0.x, f0.y, f0.z, f0.w, f1.x, f1.y, f1.z, f1.w};
#pragma unroll
                    for (int j = 0; j < 8; ++j) {
                        hh[j] = __float2bfloat16(fv[j]);
                        ll[j] = __float2bfloat16(fv[j] - __bfloat162float(hh[j]));
                    }
                } else {
#pragma unroll
                    for (int j = 0; j < 8; ++j) { hh[j] = __nv_bfloat16(0.f); ll[j] = __nv_bfloat16(0.f); }
                }
                *reinterpret_cast<uint4*>(bAh + off) = *reinterpret_cast<const uint4*>(hh);
                *reinterpret_cast<uint4*>(bAl + off) = *reinterpret_cast<const uint4*>(ll);
            } else {
                cpa16(bAh + off, Ah + (size_t)(m0 + r) * HID + k0 + qd * 8);
                cpa16(bAl + off, Al + (size_t)(m0 + r) * HID + k0 + qd * 8);
            }
        }
#pragma unroll
        for (int u = tid; u < NCOLS * 4; u += 256) {
            const int r = u >> 2, qd = u & 3;
            const int off = r * SPAD + qd * 8;
            cpa16(bBh + off, Wh + (size_t)r * HID + k0 + qd * 8);
            cpa16(bBl + off, Wl + (size_t)r * HID + k0 + qd * 8);
        }
        asm volatile("cp.async.commit_group;" ::: "memory");
    };

    stage(0);
    for (int c = 0; c < nchunks; ++c) {
        if (c + 1 < nchunks) {
            stage(c + 1);
            asm volatile("cp.async.wait_group 1;" ::: "memory");
        } else {
            asm volatile("cp.async.wait_group 0;" ::: "memory");
        }
        __syncthreads();

        const uint32_t bufB = smem_u32(smem + (c & 1) * SST);
        const uint32_t aH = bufB + aLane;
        const uint32_t aL = bufB + SA * 2 + aLane;
        const uint32_t bH = bufB + 2 * SA * 2 + bLane;
        const uint32_t bL = bufB + (2 * SA + SB) * 2 + bLane;

#pragma unroll
        for (int kk = 0; kk < 32; kk += 16) {
            uint32_t afh[2][4], afl[2][4];
#pragma unroll
            for (int mi = 0; mi < 2; ++mi) {
                ldsm_x4(afh[mi], aH + (uint32_t)(mi * 32 * SPAD + 2 * kk));
                ldsm_x4(afl[mi], aL + (uint32_t)(mi * 32 * SPAD + 2 * kk));
            }
#pragma unroll
            for (int njp = 0; njp < NJP; ++njp) {
                uint32_t bh[4], bl[4];
                ldsm_x4(bh, bH + (uint32_t)(njp * 32 * SPAD + 2 * kk));
                ldsm_x4(bl, bL + (uint32_t)(njp * 32 * SPAD + 2 * kk));
#pragma unroll
                for (int mi = 0; mi < 2; ++mi) {
                    mma16816(acc[mi][2 * njp],     afh[mi], bh);
                    mma16816(acc[mi][2 * njp],     afh[mi], bl);
                    mma16816(acc[mi][2 * njp],     afl[mi], bh);
                    mma16816(acc[mi][2 * njp + 1], afh[mi], bh + 2);
                    mma16816(acc[mi][2 * njp + 1], afh[mi], bl + 2);
                    mma16816(acc[mi][2 * njp + 1], afl[mi], bh + 2);
                }
            }
        }
        __syncthreads();
    }

    // ---- epilogue ----
#pragma unroll
    for (int mi = 0; mi < 2; ++mi)
#pragma unroll
        for (int nj = 0; nj < NJ; ++nj)
#pragma unroll
            for (int q = 0; q < 4; ++q) {
                float v = acc[mi][nj][q];
                if (MODE == 0 || MODE == 2) v += bias[nw + 8 * nj + tig * 2 + (q & 1)];
                acc[mi][nj][q] = gelu_f(v);
            }

    if (MODE == 0) {          // ENC
#pragma unroll
        for (int mi = 0; mi < 2; ++mi)
#pragma unroll
            for (int half = 0; half < 2; ++half) {
                const int m = m0 + mw + 16 * mi + gid + 8 * half;
                if (m >= M) continue;
#pragma unroll
                for (int nj = 0; nj < NJ; ++nj) {
                    const int ng = nw + 8 * nj + tig * 2;
                    const float v0 = acc[mi][nj][2 * half];
                    const float v1 = acc[mi][nj][2 * half + 1];
                    *reinterpret_cast<float2*>(outF + (size_t)m * NCOLS + ng) =
                        make_float2(v0, v1);
                    __nv_bfloat162 hv, lv;
                    hv.x = __float2bfloat16(v0); hv.y = __float2bfloat16(v1);
                    lv.x = __float2bfloat16(v0 - __bfloat162float(hv.x));
                    lv.y = __float2bfloat16(v1 - __bfloat162float(hv.y));
                    *reinterpret_cast<__nv_bfloat162*>(&outH[(size_t)m * HID + ng]) = hv;
                    *reinterpret_cast<__nv_bfloat162*>(&outL[(size_t)m * HID + ng]) = lv;
                }
            }
    } else if (MODE == 1) {   // SAGE: LN + residual + splits
#pragma unroll
        for (int mi = 0; mi < 2; ++mi)
#pragma unroll
            for (int half = 0; half < 2; ++half) {
                float s = 0.0f, q2 = 0.0f;
#pragma unroll
                for (int nj = 0; nj < NJ; ++nj) {
                    const float v0 = acc[mi][nj][2 * half];
                    const float v1 = acc[mi][nj][2 * half + 1];
                    s += v0 + v1;
                    q2 = fmaf(v0, v0, fmaf(v1, v1, q2));
                }
                s  += __shfl_xor_sync(0xffffffffu, s, 1);
                q2 += __shfl_xor_sync(0xffffffffu, q2, 1);
                s  += __shfl_xor_sync(0xffffffffu, s, 2);
                q2 += __shfl_xor_sync(0xffffffffu, q2, 2);
                if (tig == 0) {
                    const int rl = mw + 16 * mi + gid + 8 * half;
                    red[rl][wid & 3][0] = s;
                    red[rl][wid & 3][1] = q2;
                }
            }
        __syncthreads();
#pragma unroll
        for (int mi = 0; mi < 2; ++mi)
#pragma unroll
            for (int half = 0; half < 2; ++half) {
                const int rl = mw + 16 * mi + gid + 8 * half;
                const float ts = red[rl][0][0] + red[rl][1][0] + red[rl][2][0] + red[rl][3][0];
                const float tq = red[rl][0][1] + red[rl][1][1] + red[rl][2][1] + red[rl][3][1];
                const float mu = ts * (1.0f / NCOLS);
                const float var = tq * (1.0f / NCOLS) - mu * mu;
                const float rstd = rsqrtf(var + 1e-5f);
                const int m = m0 + rl;
                if (m >= M) continue;
#pragma unroll
                for (int nj = 0; nj < NJ; ++nj) {
                    const int ng = nw + 8 * nj + tig * 2;
                    const float2 hold = *reinterpret_cast<const float2*>(outF + (size_t)m * NCOLS + ng);
                    const float y0 = (acc[mi][nj][2 * half]     - mu) * rstd * gamma[ng]     + beta[ng];
                    const float y1 = (acc[mi][nj][2 * half + 1] - mu) * rstd * gamma[ng + 1] + beta[ng + 1];
                    const float h0 = hold.x + y0;
                    const float h1 = hold.y + y1;
                    *reinterpret_cast<float2*>(outF + (size_t)m * NCOLS + ng) = make_float2(h0, h1);
                    __nv_bfloat162 hv, lv;
                    hv.x = __float2bfloat16(h0); hv.y = __float2bfloat16(h1);
                    lv.x = __float2bfloat16(h0 - __bfloat162float(hv.x));
                    lv.y = __float2bfloat16(h1 - __bfloat162float(hv.y));
                    *reinterpret_cast<__nv_bfloat162*>(&outH[(size_t)m * HID + ng]) = hv;
                    *reinterpret_cast<__nv_bfloat162*>(&outL[(size_t)m * HID + ng]) = lv;
                }
            }
    } else {                  // MODE 2: CLS
#pragma unroll
        for (int mi = 0; mi < 2; ++mi)
#pragma unroll
            for (int half = 0; half < 2; ++half) {
                float d = 0.0f;
#pragma unroll
                for (int nj = 0; nj < NJ; ++nj) {
                    const int ng = nw + 8 * nj + tig * 2;
                    d = fmaf(acc[mi][nj][2 * half], cw2[ng],
                        fmaf(acc[mi][nj][2 * half + 1], cw2[ng + 1], d));
                }
                d += __shfl_xor_sync(0xffffffffu, d, 1);
                d += __shfl_xor_sync(0xffffffffu, d, 2);
                if (tig == 0) {
                    const int rl = mw + 16 * mi + gid + 8 * half;
                    red[rl][wid & 3][0] = d;
                }
            }
        __syncthreads();
        if ((wid & 3) == 0 && tig == 0) {
#pragma unroll
            for (int mi = 0; mi < 2; ++mi)
#pragma unroll
                for (int half = 0; half < 2; ++half) {
                    const int rl = mw + 16 * mi + gid + 8 * half;
                    const int m = m0 + rl;
                    if (m >= M) continue;
                    const float logit = red[rl][0][0] + red[rl][1][0] +
                                        red[rl][2][0] + red[rl][3][0] + cb2[0];
                    outS[m] = 1.0f / (1.0f + expf(-logit));
                }
        }
    }
}

// ================= neighbor aggregation (emits bf16 split) ====================
__global__ void agg_kernel(const float* __restrict__ h, const int* __restrict__ nidx,
                           const float* __restrict__ nw,
                           __nv_bfloat16* __restrict__ gh, __nv_bfloat16* __restrict__ gl) {
    const int n = blockIdx.x;
    const int d = threadIdx.x;
    __shared__ int   sidx[KNB];
    __shared__ float sw  [KNB];
    if (d < KNB) { sidx[d] = nidx[n * KNB + d]; sw[d] = nw[n * KNB + d]; }
    __syncthreads();
    float acc = 0.0f;
#pragma unroll
    for (int k = 0; k < KNB; ++k)
        acc = fmaf(sw[k], h[(size_t)sidx[k] * HID + d], acc);
    const __nv_bfloat16 hi = __float2bfloat16(acc);
    gh[(size_t)n * HID + d] = hi;
    gl[(size_t)n * HID + d] = __float2bfloat16(acc - __bfloat162float(hi));
}

// ================= launch =======================================================
extern "C" void kernel_launch(void* const* d_in, const int* in_sizes, int n_in,
                              void* d_out, int out_size) {
    const float* feats  = (const float*)d_in[0];
    const float* cents  = (const float*)d_in[1];
    const float* enc_w  = (const float*)d_in[2];
    const float* enc_b  = (const float*)d_in[3];
    const float* g1_ws  = (const float*)d_in[4];
    const float* g1_wn  = (const float*)d_in[5];
    const float* g1_g   = (const float*)d_in[6];
    const float* g1_b   = (const float*)d_in[7];
    const float* g2_ws  = (const float*)d_in[8];
    const float* g2_wn  = (const float*)d_in[9];
    const float* g2_g   = (const float*)d_in[10];
    const float* g2_b   = (const float*)d_in[11];
    const float* cls_w1 = (const float*)d_in[12];
    const float* cls_b1 = (const float*)d_in[13];
    const float* cls_w2 = (const float*)d_in[14];
    const float* cls_b2 = (const float*)d_in[15];
    float* out = (float*)d_out;

    float *p_h, *p_nw;
    int* p_nidx;
    __nv_bfloat16 *p_ah, *p_al, *p_gh, *p_gl, *p_wh, *p_wl;
    cudaGetSymbolAddress((void**)&p_h,    g_h);
    cudaGetSymbolAddress((void**)&p_nidx, g_nidx);
    cudaGetSymbolAddress((void**)&p_nw,   g_nw);
    cudaGetSymbolAddress((void**)&p_ah,   g_ah);
    cudaGetSymbolAddress((void**)&p_al,   g_al);
    cudaGetSymbolAddress((void**)&p_gh,   g_gh);
    cudaGetSymbolAddress((void**)&p_gl,   g_gl);
    cudaGetSymbolAddress((void**)&p_wh,   g_wh);
    cudaGetSymbolAddress((void**)&p_wl,   g_wl);

    const int M = NPTS;
    const int NBLK = (M + 63) / 64;   // 188
    const int SM256 = (2 * (2 * 64 * SPAD + 2 * 256 * SPAD)) * (int)sizeof(__nv_bfloat16);
    const int SM128 = (2 * (2 * 64 * SPAD + 2 * 128 * SPAD)) * (int)sizeof(__nv_bfloat16);

    cudaFuncSetAttribute(hmma_gemm_kernel<256, 0, false, true >,
                         cudaFuncAttributeMaxDynamicSharedMemorySize, SM256);
    cudaFuncSetAttribute(hmma_gemm_kernel<256, 1, true,  false>,
                         cudaFuncAttributeMaxDynamicSharedMemorySize, SM256);
    cudaFuncSetAttribute(hmma_gemm_kernel<128, 2, false, false>,
                         cudaFuncAttributeMaxDynamicSharedMemorySize, SM128);

    cudaStream_t s2;
    cudaStreamCreateWithFlags(&s2, cudaStreamNonBlocking);
    cudaEvent_t evF, evJ;
    cudaEventCreateWithFlags(&evF, cudaEventDisableTiming);
    cudaEventCreateWithFlags(&evJ, cudaEventDisableTiming);
    cudaEventRecord(evF, 0);
    cudaStreamWaitEvent(s2, evF, 0);

    // ---- s2: KNN (2 launches), starts immediately ----
    knn_build_kernel<<<1, 1024, 0, s2>>>(cents);
    knn_query_kernel<<<(NPTS * 32 + 255) / 256, 256, 0, s2>>>(p_nidx, p_nw);
    cudaEventRecord(evJ, s2);

    // ---- main: encoder-slice split -> encoder -> remaining splits in slack ----
    split_w_kernel<<<(WENC + 255) / 256, 256>>>(
        enc_w, g1_ws, g1_wn, g2_ws, g2_wn, cls_w1, 0, WENC);
    hmma_gemm_kernel<256, 0, false, true><<<NBLK, 256, SM256>>>(
        nullptr, nullptr, feats, p_wh + 0, p_wl + 0,
        nullptr, nullptr, nullptr, nullptr,
        enc_b, nullptr, nullptr, nullptr, nullptr, nullptr,
        p_h, p_ah, p_al, M);
    split_w_kernel<<<(WTOT - WENC + 255) / 256, 256>>>(
        enc_w, g1_ws, g1_wn, g2_ws, g2_wn, cls_w1, WENC, WTOT);

    // join: agg needs knn graph + h
    cudaStreamWaitEvent(0, evJ, 0);

    // ---- SAGE layer 1 ----
    agg_kernel<<<NPTS, HID>>>(p_h, p_nidx, p_nw, p_gh, p_gl);
    hmma_gemm_kernel<256, 1, true, false><<<NBLK, 256, SM256>>>(
        p_ah, p_al, nullptr, p_wh + 65536, p_wl + 65536,
        p_gh, p_gl, p_wh + 131072, p_wl + 131072,
        nullptr, g1_g, g1_b, nullptr, nullptr, nullptr,
        p_h, p_ah, p_al, M);

    // ---- SAGE layer 2 ----
    agg_kernel<<<NPTS, HID>>>(p_h, p_nidx, p_nw, p_gh, p_gl);
    hmma_gemm_kernel<256, 1, true, false><<<NBLK, 256, SM256>>>(
        p_ah, p_al, nullptr, p_wh + 196608, p_wl + 196608,
        p_gh, p_gl, p_wh + 262144, p_wl + 262144,
        nullptr, g2_g, g2_b, nullptr, nullptr, nullptr,
        p_h, p_ah, p_al, M);

    // ---- classifier (fused dot + sigmoid) ----
    hmma_gemm_kernel<128, 2, false, false><<<NBLK, 256, SM128>>>(
        p_ah, p_al, nullptr, p_wh + 327680, p_wl + 327680,
        nullptr, nullptr, nullptr, nullptr,
        cls_b1, nullptr, nullptr, cls_w2, cls_b2, out,
        nullptr, nullptr, nullptr, M);
}

// round 14
// speedup vs baseline: 1.3614x; 1.3614x over previous
#include <cuda_runtime.h>
#include <cuda_bf16.h>
#include <cstdint>
#include <cfloat>
#include <math.h>

#define NPTS 12000
#define MPAD 12032
#define HID  256
#define KNB  16
#define G    64
#define NCELL (G * G)

// ---------------- scratch (allocation-free: __device__ globals) --------------
__device__ float g_h   [MPAD * HID];
__device__ int   g_nidx[NPTS * KNB];
__device__ float g_nw  [NPTS * KNB];

__device__ __nv_bfloat16 g_ah[MPAD * HID], g_al[MPAD * HID];   // h split
__device__ __nv_bfloat16 g_gh[MPAD * HID], g_gl[MPAD * HID];   // agg split
#define WTOT 360448
#define WENC 65536
__device__ __nv_bfloat16 g_wh[WTOT], g_wl[WTOT];
// slots: enc=0, g1ws=65536, g1wn=131072, g2ws=196608, g2wn=262144, cls=327680

// grid-knn scratch
__device__ unsigned int g_bbox[4];
__device__ int    g_cellstart[NCELL + 1];
__device__ float2 g_pts [NPTS];
__device__ int    g_sidx[NPTS];

__device__ __forceinline__ float gelu_f(float x) {
    return 0.5f * x * (1.0f + erff(x * 0.70710678118654752440f));
}

__device__ __forceinline__ unsigned int fenc(float f) {
    unsigned int u = __float_as_uint(f);
    return (u & 0x80000000u) ? ~u : (u | 0x80000000u);
}
__device__ __forceinline__ float fdec(unsigned int u) {
    return __uint_as_float((u & 0x80000000u) ? (u ^ 0x80000000u) : ~u);
}

__device__ __forceinline__ uint32_t smem_u32(const void* p) {
    uint32_t a;
    asm("{ .reg .u64 t; cvta.to.shared.u64 t, %1; cvt.u32.u64 %0, t; }" : "=r"(a) : "l"(p));
    return a;
}
__device__ __forceinline__ void cpa16(__nv_bfloat16* dst, const __nv_bfloat16* src) {
    const uint32_t d = smem_u32(dst);
    asm volatile("cp.async.cg.shared.global [%0], [%1], 16;" :: "r"(d), "l"(src) : "memory");
}
__device__ __forceinline__ void ldsm_x4(uint32_t* r, uint32_t addr) {
    asm volatile("ldmatrix.sync.aligned.m8n8.x4.shared.b16 {%0,%1,%2,%3}, [%4];"
                 : "=r"(r[0]), "=r"(r[1]), "=r"(r[2]), "=r"(r[3]) : "r"(addr));
}

// HMMA: D(f32) += A(bf16,row) * B(bf16,col), m16n8k16
__device__ __forceinline__ void mma16816(float* c, const uint32_t* a, const uint32_t* b) {
    asm volatile(
        "mma.sync.aligned.m16n8k16.row.col.f32.bf16.bf16.f32 "
        "{%0,%1,%2,%3}, {%4,%5,%6,%7}, {%8,%9}, {%0,%1,%2,%3};"
        : "+f"(c[0]), "+f"(c[1]), "+f"(c[2]), "+f"(c[3])
        : "r"(a[0]), "r"(a[1]), "r"(a[2]), "r"(a[3]), "r"(b[0]), "r"(b[1]));
}

// ================= KNN build: ONE CTA does bbox+count+scan+scatter =============
__global__ __launch_bounds__(1024) void knn_build_kernel(const float* __restrict__ cents) {
    __shared__ int   scnt[NCELL];
    __shared__ float rmnx[32], rmxx[32], rmny[32], rmxy[32];
    __shared__ float sbb[4];
    __shared__ int   wsum[32];
    const int t = threadIdx.x;
    const int lane = t & 31;
    const int warp = t >> 5;

    float2 pts[12];
    int np = 0;
    for (int i = t; i < NPTS; i += 1024) pts[np++] = *reinterpret_cast<const float2*>(cents + 2 * i);

    float xmn = FLT_MAX, xmx = -FLT_MAX, ymn = FLT_MAX, ymx = -FLT_MAX;
    for (int j = 0; j < np; ++j) {
        xmn = fminf(xmn, pts[j].x); xmx = fmaxf(xmx, pts[j].x);
        ymn = fminf(ymn, pts[j].y); ymx = fmaxf(ymx, pts[j].y);
    }
#pragma unroll
    for (int o = 16; o > 0; o >>= 1) {
        xmn = fminf(xmn, __shfl_xor_sync(0xffffffffu, xmn, o));
        xmx = fmaxf(xmx, __shfl_xor_sync(0xffffffffu, xmx, o));
        ymn = fminf(ymn, __shfl_xor_sync(0xffffffffu, ymn, o));
        ymx = fmaxf(ymx, __shfl_xor_sync(0xffffffffu, ymx, o));
    }
    if (lane == 0) { rmnx[warp] = xmn; rmxx[warp] = xmx; rmny[warp] = ymn; rmxy[warp] = ymx; }
    __syncthreads();
    if (t == 0) {
        float a = rmnx[0], b = rmxx[0], c = rmny[0], d = rmxy[0];
        for (int i = 1; i < 32; ++i) {
            a = fminf(a, rmnx[i]); b = fmaxf(b, rmxx[i]);
            c = fminf(c, rmny[i]); d = fmaxf(d, rmxy[i]);
        }
        sbb[0] = a; sbb[1] = b; sbb[2] = c; sbb[3] = d;
        g_bbox[0] = fenc(a); g_bbox[1] = fenc(b);
        g_bbox[2] = fenc(c); g_bbox[3] = fenc(d);
    }
    for (int c = t; c < NCELL; c += 1024) scnt[c] = 0;
    __syncthreads();

    const float xmin = sbb[0], ymin = sbb[2];
    const float rx = fmaxf(sbb[1] - xmin, 1e-20f);
    const float ry = fmaxf(sbb[3] - ymin, 1e-20f);
    const float iwx = (float)G / rx, iwy = (float)G / ry;

    int cellid[12];
    for (int j = 0; j < np; ++j) {
        int cx = (int)((pts[j].x - xmin) * iwx); cx = min(max(cx, 0), G - 1);
        int cy = (int)((pts[j].y - ymin) * iwy); cy = min(max(cy, 0), G - 1);
        cellid[j] = cy * G + cx;
        atomicAdd(&scnt[cellid[j]], 1);
    }
    __syncthreads();

    const int base = t * 4;
    int loc[4];
    int s = 0;
#pragma unroll
    for (int j = 0; j < 4; ++j) { loc[j] = s; s += scnt[base + j]; }
    int v = s;
#pragma unroll
    for (int o = 1; o < 32; o <<= 1) {
        const int n = __shfl_up_sync(0xffffffffu, v, o);
        if (lane >= o) v += n;
    }
    if (lane == 31) wsum[warp] = v;
    __syncthreads();
    if (t == 0) {
        int run = 0;
        for (int i = 0; i < 32; ++i) { const int tmp = wsum[i]; wsum[i] = run; run += tmp; }
    }
    __syncthreads();
    const int pre = wsum[warp] + (v - s);
#pragma unroll
    for (int j = 0; j < 4; ++j) loc[j] += pre;
#pragma unroll
    for (int j = 0; j < 4; ++j) g_cellstart[base + j] = loc[j];
    if (t == 1023) g_cellstart[NCELL] = NPTS;
    __syncthreads();
#pragma unroll
    for (int j = 0; j < 4; ++j) scnt[base + j] = loc[j];
    __syncthreads();

    for (int j = 0; j < np; ++j) {
        const int slot = atomicAdd(&scnt[cellid[j]], 1);
        g_pts [slot] = pts[j];
        g_sidx[slot] = t + 1024 * j;
    }
}

__device__ __forceinline__ void grid_params(float& xmin, float& ymin,
                                            float& iwx, float& iwy,
                                            float& wx, float& wy) {
    xmin = fdec(g_bbox[0]);
    const float xmax = fdec(g_bbox[1]);
    ymin = fdec(g_bbox[2]);
    const float ymax = fdec(g_bbox[3]);
    const float rx = fmaxf(xmax - xmin, 1e-20f);
    const float ry = fmaxf(ymax - ymin, 1e-20f);
    iwx = (float)G / rx; iwy = (float)G / ry;
    wx = rx / (float)G;  wy = ry / (float)G;
}

__device__ __forceinline__ int cell_x(float x, float xmin, float iwx) {
    int c = (int)((x - xmin) * iwx);
    return min(max(c, 0), G - 1);
}

// ================= KNN query: warp/query, LANE-DISTRIBUTED shared top-16 ======
// Slot i lives in lane i (lanes 16-31 hold -inf). Semantically identical to the
// warp-replicated top-16 (same acceptance sequence, same exact global-16th-best
// threshold), but insert = 1 ballot + owner-replace + 5-shfl max (no 16-deep
// ALU loops), and no final merge (slots already distributed).
__global__ void knn_query_kernel(int* __restrict__ nidx, float* __restrict__ nw) {
    const int w = (blockIdx.x * blockDim.x + threadIdx.x) >> 5;
    const int lane = threadIdx.x & 31;
    if (w >= NPTS) return;
    const int s = w;
    const float2 q = g_pts[s];
    const int i = g_sidx[s];

    float xmin, ymin, iwx, iwy, wx, wy;
    grid_params(xmin, ymin, iwx, iwy, wx, wy);
    const int cx = cell_x(q.x, xmin, iwx);
    const int cy = cell_x(q.y, ymin, iwy);

    float slotval = (lane < KNB) ? FLT_MAX : -FLT_MAX;
    int   slotid  = 0;
    float maxv = FLT_MAX;     // warp-agreed current 16th best (max over slots)

    for (int r = 0; r < G; ++r) {
        const int ylo = max(cy - r, 0), yhi = min(cy + r, G - 1);
        for (int vy = ylo; vy <= yhi; ++vy) {
            const bool edge_row = (vy == cy - r) || (vy == cy + r);
            int ps0 = 0, pe0 = 0, ps1 = 0, pe1 = 0;
            if (edge_row) {
                const int xl = max(cx - r, 0), xh = min(cx + r, G - 1);
                ps0 = g_cellstart[vy * G + xl];
                pe0 = g_cellstart[vy * G + xh + 1];
            } else {
                if (cx - r >= 0) {
                    ps0 = g_cellstart[vy * G + cx - r];
                    pe0 = g_cellstart[vy * G + cx - r + 1];
                }
                if (cx + r <= G - 1) {
                    ps1 = g_cellstart[vy * G + cx + r];
                    pe1 = g_cellstart[vy * G + cx + r + 1];
                }
            }
#pragma unroll
            for (int seg = 0; seg < 2; ++seg) {
                const int ps = seg ? ps1 : ps0;
                const int pe = seg ? pe1 : pe0;
                for (int p0 = ps; p0 < pe; p0 += 32) {
                    const int p = p0 + lane;
                    float d2 = FLT_MAX;
                    if (p < pe && p != s) {
                        const float2 f = g_pts[p];
                        const float dx = q.x - f.x;
                        const float dy = q.y - f.y;
                        d2 = fmaf(dx, dx, dy * dy);
                    }
                    unsigned int m = __ballot_sync(0xffffffffu, d2 < maxv);
                    while (m) {
                        const int l = __ffs(m) - 1;
                        m &= m - 1;
                        const float dd = __shfl_sync(0xffffffffu, d2, l);
                        if (dd < maxv) {
                            const int pp = __shfl_sync(0xffffffffu, p, l);
                            // owner = first lane whose slot holds the current max
                            const unsigned int own =
                                __ballot_sync(0xffffffffu, slotval == maxv);
                            const int ol = __ffs(own) - 1;
                            if (lane == ol) { slotval = dd; slotid = pp; }
                            // refresh warp max of slots (lanes>=16 hold -inf)
                            float mx = slotval;
#pragma unroll
                            for (int o = 16; o > 0; o >>= 1)
                                mx = fmaxf(mx, __shfl_xor_sync(0xffffffffu, mx, o));
                            maxv = mx;
                        }
                    }
                }
            }
        }
        if (maxv < FLT_MAX) {
            const float bl = (cx - r > 0)     ? q.x - (xmin + (float)(cx - r) * wx)     : FLT_MAX;
            const float br = (cx + r < G - 1) ? (xmin + (float)(cx + r + 1) * wx) - q.x : FLT_MAX;
            const float bb = (cy - r > 0)     ? q.y - (ymin + (float)(cy - r) * wy)     : FLT_MAX;
            const float bt = (cy + r < G - 1) ? (ymin + (float)(cy + r + 1) * wy) - q.y : FLT_MAX;
            const float b = fminf(fminf(bl, br), fminf(bb, bt));
            if (b == FLT_MAX || (b > 0.0f && b * b > maxv)) break;
        }
    }

    // lanes 0..15 hold the 16 winners directly; rescore with reference rounding
    float invd = 0.0f;
    int oid = 0;
    if (lane < KNB) {
        const float2 f = g_pts[slotid];
        oid = g_sidx[slotid];
        const float xi = q.x, yi = q.y;
        const float sqi = __fadd_rn(__fmul_rn(xi, xi), __fmul_rn(yi, yi));
        const float sqj = __fadd_rn(__fmul_rn(f.x, f.x), __fmul_rn(f.y, f.y));
        const float dot = __fadd_rn(__fmul_rn(xi, f.x), __fmul_rn(yi, f.y));
        const float d2  = __fsub_rn(__fadd_rn(sqi, sqj), __fmul_rn(2.0f, dot));
        const float dist = sqrtf(fmaxf(d2, 0.0f));
        invd = 1.0f / fmaxf(dist, 1e-4f);
    }
    float tot = invd;
#pragma unroll
    for (int o = 16; o > 0; o >>= 1)
        tot += __shfl_xor_sync(0xffffffffu, tot, o);
    if (lane < KNB) {
        nidx[i * KNB + lane] = oid;
        nw  [i * KNB + lane] = invd / fmaxf(tot, 1e-8f);
    }
}

// ================= weight split (ranged) =======================================
__global__ void split_w_kernel(const float* __restrict__ w0, const float* __restrict__ w1,
                               const float* __restrict__ w2, const float* __restrict__ w3,
                               const float* __restrict__ w4, const float* __restrict__ w5,
                               int lo, int hi) {
    const int i = lo + blockIdx.x * blockDim.x + threadIdx.x;
    if (i >= hi) return;
    float x;
    if      (i < 65536)  x = w0[i];
    else if (i < 131072) x = w1[i - 65536];
    else if (i < 196608) x = w2[i - 131072];
    else if (i < 262144) x = w3[i - 196608];
    else if (i < 327680) x = w4[i - 262144];
    else                 x = w5[i - 327680];
    const __nv_bfloat16 h = __float2bfloat16(x);
    g_wh[i] = h;
    g_wl[i] = __float2bfloat16(x - __bfloat162float(h));
}

// ================= HMMA GEMM: fused epilogues ==================================
#define SPAD 40
template <int NCOLS, int MODE, bool DUAL, bool CONVA>
__global__ __launch_bounds__(256, 2) void hmma_gemm_kernel(
    const __nv_bfloat16* __restrict__ a1h, const __nv_bfloat16* __restrict__ a1l,
    const float* __restrict__ a1f,
    const __nv_bfloat16* __restrict__ w1h, const __nv_bfloat16* __restrict__ w1l,
    const __nv_bfloat16* __restrict__ a2h, const __nv_bfloat16* __restrict__ a2l,
    const __nv_bfloat16* __restrict__ w2h, const __nv_bfloat16* __restrict__ w2l,
    const float* __restrict__ bias,
    const float* __restrict__ gamma, const float* __restrict__ beta,
    const float* __restrict__ cw2, const float* __restrict__ cb2,
    float* __restrict__ outS,
    float* outF,
    __nv_bfloat16* __restrict__ outH, __nv_bfloat16* __restrict__ outL, int M) {
    extern __shared__ __nv_bfloat16 smem[];
    __shared__ float red[64][4][2];

    constexpr int SA = 64 * SPAD;
    constexpr int SB = NCOLS * SPAD;
    constexpr int SST = 2 * SA + 2 * SB;
    constexpr int NJ = NCOLS / 32;
    constexpr int NJP = NJ / 2;

    const int tid  = threadIdx.x;
    const int wid  = tid >> 5;
    const int lane = tid & 31;
    const int gid  = lane >> 2;
    const int tig  = lane & 3;
    const int m0 = blockIdx.x * 64;
    const int mw = (wid >> 2) * 32;
    const int nw = (wid & 3) * (NCOLS / 4);
    const int nchunks = DUAL ? 16 : 8;

    const uint32_t aLane = (uint32_t)(((mw + (lane & 15)) * SPAD + ((lane >> 4) & 1) * 8) * 2);
    const uint32_t bLane = (uint32_t)(((nw + 8 * ((lane >> 4) & 1) + (lane & 7)) * SPAD +
                                       ((lane >> 3) & 1) * 8) * 2);

    float acc[2][NJ][4];
#pragma unroll
    for (int a = 0; a < 2; ++a)
#pragma unroll
        for (int b = 0; b < NJ; ++b)
#pragma unroll
            for (int c = 0; c < 4; ++c) acc[a][b][c] = 0.0f;

    auto stage = [&](int c) {
        const int k0 = (c & 7) * 32;
        const bool s1 = DUAL && (c >= 8);
        const __nv_bfloat16* Ah = s1 ? a2h : a1h;
        const __nv_bfloat16* Al = s1 ? a2l : a1l;
        const __nv_bfloat16* Wh = s1 ? w2h : w1h;
        const __nv_bfloat16* Wl = s1 ? w2l : w1l;
        __nv_bfloat16* buf = smem + (c & 1) * SST;
        __nv_bfloat16* bAh = buf;
        __nv_bfloat16* bAl = buf + SA;
        __nv_bfloat16* bBh = buf + 2 * SA;
        __nv_bfloat16* bBl = buf + 2 * SA + SB;
        {
            const int r = tid >> 2, qd = tid & 3;
            const int off = r * SPAD + qd * 8;
            if (CONVA) {
                const int mg = m0 + r;
                __align__(16) __nv_bfloat16 hh[8], ll[8];
                if (mg < M) {
                    const float* fp = a1f + (size_t)mg * HID + k0 + qd * 8;
                    const float4 f0 = *reinterpret_cast<const float4*>(fp);
                    const float4 f1 = *reinterpret_cast<const float4*>(fp + 4);
                    const float fv[8] = {f0.x, f0.y, f0.z, f0.w, f1.x, f1.y, f1.z, f1.w};
#pragma unroll
                    for (int j = 0; j < 8; ++j) {
                        hh[j] = __float2bfloat16(fv[j]);
                        ll[j] = __float2bfloat16(fv[j] - __bfloat162float(hh[j]));
                    }
                } else {
#pragma unroll
                    for (int j = 0; j < 8; ++j) { hh[j] = __nv_bfloat16(0.f); ll[j] = __nv_bfloat16(0.f); }
                }
                *reinterpret_cast<uint4*>(bAh + off) = *reinterpret_cast<const uint4*>(hh);
                *reinterpret_cast<uint4*>(bAl + off) = *reinterpret_cast<const uint4*>(ll);
            } else {
                cpa16(bAh + off, Ah + (size_t)(m0 + r) * HID + k0 + qd * 8);
                cpa16(bAl + off, Al + (size_t)(m0 + r) * HID + k0 + qd * 8);
            }
        }
#pragma unroll
        for (int u = tid; u < NCOLS * 4; u += 256) {
            const int r = u >> 2, qd = u & 3;
            const int off = r * SPAD + qd * 8;
            cpa16(bBh + off, Wh + (size_t)r * HID + k0 + qd * 8);
            cpa16(bBl + off, Wl + (size_t)r * HID + k0 + qd * 8);
        }
        asm volatile("cp.async.commit_group;" ::: "memory");
    };

    stage(0);
    for (int c = 0; c < nchunks; ++c) {
        if (c + 1 < nchunks) {
            stage(c + 1);
            asm volatile("cp.async.wait_group 1;" ::: "memory");
        } else {
            asm volatile("cp.async.wait_group 0;" ::: "memory");
        }
        __syncthreads();

        const uint32_t bufB = smem_u32(smem + (c & 1) * SST);
        const uint32_t aH = bufB + aLane;
        const uint32_t aL = bufB + SA * 2 + aLane;
        const uint32_t bH = bufB + 2 * SA * 2 + bLane;
        const uint32_t bL = bufB + (2 * SA + SB) * 2 + bLane;

#pragma unroll
        for (int kk = 0; kk < 32; kk += 16) {
            uint32_t afh[2][4], afl[2][4];
#pragma unroll
            for (int mi = 0; mi < 2; ++mi) {
                ldsm_x4(afh[mi], aH + (uint32_t)(mi * 32 * SPAD + 2 * kk));
                ldsm_x4(afl[mi], aL + (uint32_t)(mi * 32 * SPAD + 2 * kk));
            }
#pragma unroll
            for (int njp = 0; njp < NJP; ++njp) {
                uint32_t bh[4], bl[4];
                ldsm_x4(bh, bH + (uint32_t)(njp * 32 * SPAD + 2 * kk));
                ldsm_x4(bl, bL + (uint32_t)(njp * 32 * SPAD + 2 * kk));
#pragma unroll
                for (int mi = 0; mi < 2; ++mi) {
                    mma16816(acc[mi][2 * njp],     afh[mi], bh);
                    mma16816(acc[mi][2 * njp],     afh[mi], bl);
                    mma16816(acc[mi][2 * njp],     afl[mi], bh);
                    mma16816(acc[mi][2 * njp + 1], afh[mi], bh + 2);
                    mma16816(acc[mi][2 * njp + 1], afh[mi], bl + 2);
                    mma16816(acc[mi][2 * njp + 1], afl[mi], bh + 2);
                }
            }
        }
        __syncthreads();
    }

    // ---- epilogue ----
#pragma unroll
    for (int mi = 0; mi < 2; ++mi)
#pragma unroll
        for (int nj = 0; nj < NJ; ++nj)
#pragma unroll
            for (int q = 0; q < 4; ++q) {
                float v = acc[mi][nj][q];
                if (MODE == 0 || MODE == 2) v += bias[nw + 8 * nj + tig * 2 + (q & 1)];
                acc[mi][nj][q] = gelu_f(v);
            }

    if (MODE == 0) {          // ENC
#pragma unroll
        for (int mi = 0; mi < 2; ++mi)
#pragma unroll
            for (int half = 0; half < 2; ++half) {
                const int m = m0 + mw + 16 * mi + gid + 8 * half;
                if (m >= M) continue;
#pragma unroll
                for (int nj = 0; nj < NJ; ++nj) {
                    const int ng = nw + 8 * nj + tig * 2;
                    const float v0 = acc[mi][nj][2 * half];
                    const float v1 = acc[mi][nj][2 * half + 1];
                    *reinterpret_cast<float2*>(outF + (size_t)m * NCOLS + ng) =
                        make_float2(v0, v1);
                    __nv_bfloat162 hv, lv;
                    hv.x = __float2bfloat16(v0); hv.y = __float2bfloat16(v1);
                    lv.x = __float2bfloat16(v0 - __bfloat162float(hv.x));
                    lv.y = __float2bfloat16(v1 - __bfloat162float(hv.y));
                    *reinterpret_cast<__nv_bfloat162*>(&outH[(size_t)m * HID + ng]) = hv;
                    *reinterpret_cast<__nv_bfloat162*>(&outL[(size_t)m * HID + ng]) = lv;
                }
            }
    } else if (MODE == 1) {   // SAGE: LN + residual + splits
#pragma unroll
        for (int mi = 0; mi < 2; ++mi)
#pragma unroll
            for (int half = 0; half < 2; ++half) {
                float s = 0.0f, q2 = 0.0f;
#pragma unroll
                for (int nj = 0; nj < NJ; ++nj) {
                    const float v0 = acc[mi][nj][2 * half];
                    const float v1 = acc[mi][nj][2 * half + 1];
                    s += v0 + v1;
                    q2 = fmaf(v0, v0, fmaf(v1, v1, q2));
                }
                s  += __shfl_xor_sync(0xffffffffu, s, 1);
                q2 += __shfl_xor_sync(0xffffffffu, q2, 1);
                s  += __shfl_xor_sync(0xffffffffu, s, 2);
                q2 += __shfl_xor_sync(0xffffffffu, q2, 2);
                if (tig == 0) {
                    const int rl = mw + 16 * mi + gid + 8 * half;
                    red[rl][wid & 3][0] = s;
                    red[rl][wid & 3][1] = q2;
                }
            }
        __syncthreads();
#pragma unroll
        for (int mi = 0; mi < 2; ++mi)
#pragma unroll
            for (int half = 0; half < 2; ++half) {
                const int rl = mw + 16 * mi + gid + 8 * half;
                const float ts = red[rl][0][0] + red[rl][1][0] + red[rl][2][0] + red[rl][3][0];
                const float tq = red[rl][0][1] + red[rl][1][1] + red[rl][2][1] + red[rl][3][1];
                const float mu = ts * (1.0f / NCOLS);
                const float var = tq * (1.0f / NCOLS) - mu * mu;
                const float rstd = rsqrtf(var + 1e-5f);
                const int m = m0 + rl;
                if (m >= M) continue;
#pragma unroll
                for (int nj = 0; nj < NJ; ++nj) {
                    const int ng = nw + 8 * nj + tig * 2;
                    const float2 hold = *reinterpret_cast<const float2*>(outF + (size_t)m * NCOLS + ng);
                    const float y0 = (acc[mi][nj][2 * half]     - mu) * rstd * gamma[ng]     + beta[ng];
                    const float y1 = (acc[mi][nj][2 * half + 1] - mu) * rstd * gamma[ng + 1] + beta[ng + 1];
                    const float h0 = hold.x + y0;
                    const float h1 = hold.y + y1;
                    *reinterpret_cast<float2*>(outF + (size_t)m * NCOLS + ng) = make_float2(h0, h1);
                    __nv_bfloat162 hv, lv;
                    hv.x = __float2bfloat16(h0); hv.y = __float2bfloat16(h1);
                    lv.x = __float2bfloat16(h0 - __bfloat162float(hv.x));
                    lv.y = __float2bfloat16(h1 - __bfloat162float(hv.y));
                    *reinterpret_cast<__nv_bfloat162*>(&outH[(size_t)m * HID + ng]) = hv;
                    *reinterpret_cast<__nv_bfloat162*>(&outL[(size_t)m * HID + ng]) = lv;
                }
            }
    } else {                  // MODE 2: CLS
#pragma unroll
        for (int mi = 0; mi < 2; ++mi)
#pragma unroll
            for (int half = 0; half < 2; ++half) {
                float d = 0.0f;
#pragma unroll
                for (int nj = 0; nj < NJ; ++nj) {
                    const int ng = nw + 8 * nj + tig * 2;
                    d = fmaf(acc[mi][nj][2 * half], cw2[ng],
                        fmaf(acc[mi][nj][2 * half + 1], cw2[ng + 1], d));
                }
                d += __shfl_xor_sync(0xffffffffu, d, 1);
                d += __shfl_xor_sync(0xffffffffu, d, 2);
                if (tig == 0) {
                    const int rl = mw + 16 * mi + gid + 8 * half;
                    red[rl][wid & 3][0] = d;
                }
            }
        __syncthreads();
        if ((wid & 3) == 0 && tig == 0) {
#pragma unroll
            for (int mi = 0; mi < 2; ++mi)
#pragma unroll
                for (int half = 0; half < 2; ++half) {
                    const int rl = mw + 16 * mi + gid + 8 * half;
                    const int m = m0 + rl;
                    if (m >= M) continue;
                    const float logit = red[rl][0][0] + red[rl][1][0] +
                                        red[rl][2][0] + red[rl][3][0] + cb2[0];
                    outS[m] = 1.0f / (1.0f + expf(-logit));
                }
        }
    }
}

// ================= neighbor aggregation (emits bf16 split) ====================
__global__ void agg_kernel(const float* __restrict__ h, const int* __restrict__ nidx,
                           const float* __restrict__ nw,
                           __nv_bfloat16* __restrict__ gh, __nv_bfloat16* __restrict__ gl) {
    const int n = blockIdx.x;
    const int d = threadIdx.x;
    __shared__ int   sidx[KNB];
    __shared__ float sw  [KNB];
    if (d < KNB) { sidx[d] = nidx[n * KNB + d]; sw[d] = nw[n * KNB + d]; }
    __syncthreads();
    float acc = 0.0f;
#pragma unroll
    for (int k = 0; k < KNB; ++k)
        acc = fmaf(sw[k], h[(size_t)sidx[k] * HID + d], acc);
    const __nv_bfloat16 hi = __float2bfloat16(acc);
    gh[(size_t)n * HID + d] = hi;
    gl[(size_t)n * HID + d] = __float2bfloat16(acc - __bfloat162float(hi));
}

// ================= launch =======================================================
extern "C" void kernel_launch(void* const* d_in, const int* in_sizes, int n_in,
                              void* d_out, int out_size) {
    const float* feats  = (const float*)d_in[0];
    const float* cents  = (const float*)d_in[1];
    const float* enc_w  = (const float*)d_in[2];
    const float* enc_b  = (const float*)d_in[3];
    const float* g1_ws  = (const float*)d_in[4];
    const float* g1_wn  = (const float*)d_in[5];
    const float* g1_g   = (const float*)d_in[6];
    const float* g1_b   = (const float*)d_in[7];
    const float* g2_ws  = (const float*)d_in[8];
    const float* g2_wn  = (const float*)d_in[9];
    const float* g2_g   = (const float*)d_in[10];
    const float* g2_b   = (const float*)d_in[11];
    const float* cls_w1 = (const float*)d_in[12];
    const float* cls_b1 = (const float*)d_in[13];
    const float* cls_w2 = (const float*)d_in[14];
    const float* cls_b2 = (const float*)d_in[15];
    float* out = (float*)d_out;

    float *p_h, *p_nw;
    int* p_nidx;
    __nv_bfloat16 *p_ah, *p_al, *p_gh, *p_gl, *p_wh, *p_wl;
    cudaGetSymbolAddress((void**)&p_h,    g_h);
    cudaGetSymbolAddress((void**)&p_nidx, g_nidx);
    cudaGetSymbolAddress((void**)&p_nw,   g_nw);
    cudaGetSymbolAddress((void**)&p_ah,   g_ah);
    cudaGetSymbolAddress((void**)&p_al,   g_al);
    cudaGetSymbolAddress((void**)&p_gh,   g_gh);
    cudaGetSymbolAddress((void**)&p_gl,   g_gl);
    cudaGetSymbolAddress((void**)&p_wh,   g_wh);
    cudaGetSymbolAddress((void**)&p_wl,   g_wl);

    const int M = NPTS;
    const int NBLK = (M + 63) / 64;   // 188
    const int SM256 = (2 * (2 * 64 * SPAD + 2 * 256 * SPAD)) * (int)sizeof(__nv_bfloat16);
    const int SM128 = (2 * (2 * 64 * SPAD + 2 * 128 * SPAD)) * (int)sizeof(__nv_bfloat16);

    cudaFuncSetAttribute(hmma_gemm_kernel<256, 0, false, true >,
                         cudaFuncAttributeMaxDynamicSharedMemorySize, SM256);
    cudaFuncSetAttribute(hmma_gemm_kernel<256, 1, true,  false>,
                         cudaFuncAttributeMaxDynamicSharedMemorySize, SM256);
    cudaFuncSetAttribute(hmma_gemm_kernel<128, 2, false, false>,
                         cudaFuncAttributeMaxDynamicSharedMemorySize, SM128);

    cudaStream_t s2;
    cudaStreamCreateWithFlags(&s2, cudaStreamNonBlocking);
    cudaEvent_t evF, evJ;
    cudaEventCreateWithFlags(&evF, cudaEventDisableTiming);
    cudaEventCreateWithFlags(&evJ, cudaEventDisableTiming);
    cudaEventRecord(evF, 0);
    cudaStreamWaitEvent(s2, evF, 0);

    // ---- s2: KNN (fused build + fast query) ----
    knn_build_kernel<<<1, 1024, 0, s2>>>(cents);
    knn_query_kernel<<<(NPTS * 32 + 255) / 256, 256, 0, s2>>>(p_nidx, p_nw);
    cudaEventRecord(evJ, s2);

    // ---- main: encoder-slice split -> encoder -> remaining splits in slack ----
    split_w_kernel<<<(WENC + 255) / 256, 256>>>(
        enc_w, g1_ws, g1_wn, g2_ws, g2_wn, cls_w1, 0, WENC);
    hmma_gemm_kernel<256, 0, false, true><<<NBLK, 256, SM256>>>(
        nullptr, nullptr, feats, p_wh + 0, p_wl + 0,
        nullptr, nullptr, nullptr, nullptr,
        enc_b, nullptr, nullptr, nullptr, nullptr, nullptr,
        p_h, p_ah, p_al, M);
    split_w_kernel<<<(WTOT - WENC + 255) / 256, 256>>>(
        enc_w, g1_ws, g1_wn, g2_ws, g2_wn, cls_w1, WENC, WTOT);

    // join: agg needs knn graph + h
    cudaStreamWaitEvent(0, evJ, 0);

    // ---- SAGE layer 1 ----
    agg_kernel<<<NPTS, HID>>>(p_h, p_nidx, p_nw, p_gh, p_gl);
    hmma_gemm_kernel<256, 1, true, false><<<NBLK, 256, SM256>>>(
        p_ah, p_al, nullptr, p_wh + 65536, p_wl + 65536,
        p_gh, p_gl, p_wh + 131072, p_wl + 131072,
        nullptr, g1_g, g1_b, nullptr, nullptr, nullptr,
        p_h, p_ah, p_al, M);

    // ---- SAGE layer 2 ----
    agg_kernel<<<NPTS, HID>>>(p_h, p_nidx, p_nw, p_gh, p_gl);
    hmma_gemm_kernel<256, 1, true, false><<<NBLK, 256, SM256>>>(
        p_ah, p_al, nullptr, p_wh + 196608, p_wl + 196608,
        p_gh, p_gl, p_wh + 262144, p_wl + 262144,
        nullptr, g2_g, g2_b, nullptr, nullptr, nullptr,
        p_h, p_ah, p_al, M);

    // ---- classifier (fused dot + sigmoid) ----
    hmma_gemm_kernel<128, 2, false, false><<<NBLK, 256, SM128>>>(
        p_ah, p_al, nullptr, p_wh + 327680, p_wl + 327680,
        nullptr, nullptr, nullptr, nullptr,
        cls_b1, nullptr, nullptr, cls_w2, cls_b2, out,
        nullptr, nullptr, nullptr, M);
}

// round 15
// speedup vs baseline: 1.4333x; 1.0528x over previous
#include <cuda_runtime.h>
#include <cuda_bf16.h>
#include <cstdint>
#include <cfloat>
#include <math.h>

#define NPTS 12000
#define MPAD 12032
#define HID  256
#define KNB  16
#define G    64
#define NCELL (G * G)

// ---------------- scratch (allocation-free: __device__ globals) --------------
__device__ float g_h   [MPAD * HID];
__device__ float g_tmp [MPAD * HID];
__device__ int   g_nidx[NPTS * KNB];
__device__ float g_nw  [NPTS * KNB];

__device__ __nv_bfloat16 g_ah[MPAD * HID], g_al[MPAD * HID];   // h split
__device__ __nv_bfloat16 g_gh[MPAD * HID], g_gl[MPAD * HID];   // agg split
#define WTOT 360448
#define WENC 65536
__device__ __nv_bfloat16 g_wh[WTOT], g_wl[WTOT];
// slots: enc=0, g1ws=65536, g1wn=131072, g2ws=196608, g2wn=262144, cls=327680

// grid-knn scratch
__device__ unsigned int g_bbox[4];
__device__ int    g_cellstart[NCELL + 1];
__device__ float2 g_pts [NPTS];
__device__ int    g_sidx[NPTS];

__device__ __forceinline__ float gelu_f(float x) {
    return 0.5f * x * (1.0f + erff(x * 0.70710678118654752440f));
}

__device__ __forceinline__ unsigned int fenc(float f) {
    unsigned int u = __float_as_uint(f);
    return (u & 0x80000000u) ? ~u : (u | 0x80000000u);
}
__device__ __forceinline__ float fdec(unsigned int u) {
    return __uint_as_float((u & 0x80000000u) ? (u ^ 0x80000000u) : ~u);
}

__device__ __forceinline__ uint32_t smem_u32(const void* p) {
    uint32_t a;
    asm("{ .reg .u64 t; cvta.to.shared.u64 t, %1; cvt.u32.u64 %0, t; }" : "=r"(a) : "l"(p));
    return a;
}
__device__ __forceinline__ void cpa16(__nv_bfloat16* dst, const __nv_bfloat16* src) {
    const uint32_t d = smem_u32(dst);
    asm volatile("cp.async.cg.shared.global [%0], [%1], 16;" :: "r"(d), "l"(src) : "memory");
}
__device__ __forceinline__ void ldsm_x4(uint32_t* r, uint32_t addr) {
    asm volatile("ldmatrix.sync.aligned.m8n8.x4.shared.b16 {%0,%1,%2,%3}, [%4];"
                 : "=r"(r[0]), "=r"(r[1]), "=r"(r[2]), "=r"(r[3]) : "r"(addr));
}

// HMMA: D(f32) += A(bf16,row) * B(bf16,col), m16n8k16
__device__ __forceinline__ void mma16816(float* c, const uint32_t* a, const uint32_t* b) {
    asm volatile(
        "mma.sync.aligned.m16n8k16.row.col.f32.bf16.bf16.f32 "
        "{%0,%1,%2,%3}, {%4,%5,%6,%7}, {%8,%9}, {%0,%1,%2,%3};"
        : "+f"(c[0]), "+f"(c[1]), "+f"(c[2]), "+f"(c[3])
        : "r"(a[0]), "r"(a[1]), "r"(a[2]), "r"(a[3]), "r"(b[0]), "r"(b[1]));
}

// ================= KNN build: ONE CTA does bbox+count+scan+scatter =============
__global__ __launch_bounds__(1024) void knn_build_kernel(const float* __restrict__ cents) {
    __shared__ int   scnt[NCELL];
    __shared__ float rmnx[32], rmxx[32], rmny[32], rmxy[32];
    __shared__ float sbb[4];
    __shared__ int   wsum[32];
    const int t = threadIdx.x;
    const int lane = t & 31;
    const int warp = t >> 5;

    float2 pts[12];
    int np = 0;
    for (int i = t; i < NPTS; i += 1024) pts[np++] = *reinterpret_cast<const float2*>(cents + 2 * i);

    float xmn = FLT_MAX, xmx = -FLT_MAX, ymn = FLT_MAX, ymx = -FLT_MAX;
    for (int j = 0; j < np; ++j) {
        xmn = fminf(xmn, pts[j].x); xmx = fmaxf(xmx, pts[j].x);
        ymn = fminf(ymn, pts[j].y); ymx = fmaxf(ymx, pts[j].y);
    }
#pragma unroll
    for (int o = 16; o > 0; o >>= 1) {
        xmn = fminf(xmn, __shfl_xor_sync(0xffffffffu, xmn, o));
        xmx = fmaxf(xmx, __shfl_xor_sync(0xffffffffu, xmx, o));
        ymn = fminf(ymn, __shfl_xor_sync(0xffffffffu, ymn, o));
        ymx = fmaxf(ymx, __shfl_xor_sync(0xffffffffu, ymx, o));
    }
    if (lane == 0) { rmnx[warp] = xmn; rmxx[warp] = xmx; rmny[warp] = ymn; rmxy[warp] = ymx; }
    __syncthreads();
    if (t == 0) {
        float a = rmnx[0], b = rmxx[0], c = rmny[0], d = rmxy[0];
        for (int i = 1; i < 32; ++i) {
            a = fminf(a, rmnx[i]); b = fmaxf(b, rmxx[i]);
            c = fminf(c, rmny[i]); d = fmaxf(d, rmxy[i]);
        }
        sbb[0] = a; sbb[1] = b; sbb[2] = c; sbb[3] = d;
        g_bbox[0] = fenc(a); g_bbox[1] = fenc(b);
        g_bbox[2] = fenc(c); g_bbox[3] = fenc(d);
    }
    for (int c = t; c < NCELL; c += 1024) scnt[c] = 0;
    __syncthreads();

    const float xmin = sbb[0], ymin = sbb[2];
    const float rx = fmaxf(sbb[1] - xmin, 1e-20f);
    const float ry = fmaxf(sbb[3] - ymin, 1e-20f);
    const float iwx = (float)G / rx, iwy = (float)G / ry;

    int cellid[12];
    for (int j = 0; j < np; ++j) {
        int cx = (int)((pts[j].x - xmin) * iwx); cx = min(max(cx, 0), G - 1);
        int cy = (int)((pts[j].y - ymin) * iwy); cy = min(max(cy, 0), G - 1);
        cellid[j] = cy * G + cx;
        atomicAdd(&scnt[cellid[j]], 1);
    }
    __syncthreads();

    const int base = t * 4;
    int loc[4];
    int s = 0;
#pragma unroll
    for (int j = 0; j < 4; ++j) { loc[j] = s; s += scnt[base + j]; }
    int v = s;
#pragma unroll
    for (int o = 1; o < 32; o <<= 1) {
        const int n = __shfl_up_sync(0xffffffffu, v, o);
        if (lane >= o) v += n;
    }
    if (lane == 31) wsum[warp] = v;
    __syncthreads();
    if (t == 0) {
        int run = 0;
        for (int i = 0; i < 32; ++i) { const int tmp = wsum[i]; wsum[i] = run; run += tmp; }
    }
    __syncthreads();
    const int pre = wsum[warp] + (v - s);
#pragma unroll
    for (int j = 0; j < 4; ++j) loc[j] += pre;
#pragma unroll
    for (int j = 0; j < 4; ++j) g_cellstart[base + j] = loc[j];
    if (t == 1023) g_cellstart[NCELL] = NPTS;
    __syncthreads();
#pragma unroll
    for (int j = 0; j < 4; ++j) scnt[base + j] = loc[j];
    __syncthreads();

    for (int j = 0; j < np; ++j) {
        const int slot = atomicAdd(&scnt[cellid[j]], 1);
        g_pts [slot] = pts[j];
        g_sidx[slot] = t + 1024 * j;
    }
}

__device__ __forceinline__ void grid_params(float& xmin, float& ymin,
                                            float& iwx, float& iwy,
                                            float& wx, float& wy) {
    xmin = fdec(g_bbox[0]);
    const float xmax = fdec(g_bbox[1]);
    ymin = fdec(g_bbox[2]);
    const float ymax = fdec(g_bbox[3]);
    const float rx = fmaxf(xmax - xmin, 1e-20f);
    const float ry = fmaxf(ymax - ymin, 1e-20f);
    iwx = (float)G / rx; iwy = (float)G / ry;
    wx = rx / (float)G;  wy = ry / (float)G;
}

__device__ __forceinline__ int cell_x(float x, float xmin, float iwx) {
    int c = (int)((x - xmin) * iwx);
    return min(max(c, 0), G - 1);
}

// ================= KNN query: warp/query, LANE-DISTRIBUTED shared top-16 ======
__global__ void knn_query_kernel(int* __restrict__ nidx, float* __restrict__ nw) {
    const int w = (blockIdx.x * blockDim.x + threadIdx.x) >> 5;
    const int lane = threadIdx.x & 31;
    if (w >= NPTS) return;
    const int s = w;
    const float2 q = g_pts[s];
    const int i = g_sidx[s];

    float xmin, ymin, iwx, iwy, wx, wy;
    grid_params(xmin, ymin, iwx, iwy, wx, wy);
    const int cx = cell_x(q.x, xmin, iwx);
    const int cy = cell_x(q.y, ymin, iwy);

    float slotval = (lane < KNB) ? FLT_MAX : -FLT_MAX;
    int   slotid  = 0;
    float maxv = FLT_MAX;

    for (int r = 0; r < G; ++r) {
        const int ylo = max(cy - r, 0), yhi = min(cy + r, G - 1);
        for (int vy = ylo; vy <= yhi; ++vy) {
            const bool edge_row = (vy == cy - r) || (vy == cy + r);
            int ps0 = 0, pe0 = 0, ps1 = 0, pe1 = 0;
            if (edge_row) {
                const int xl = max(cx - r, 0), xh = min(cx + r, G - 1);
                ps0 = g_cellstart[vy * G + xl];
                pe0 = g_cellstart[vy * G + xh + 1];
            } else {
                if (cx - r >= 0) {
                    ps0 = g_cellstart[vy * G + cx - r];
                    pe0 = g_cellstart[vy * G + cx - r + 1];
                }
                if (cx + r <= G - 1) {
                    ps1 = g_cellstart[vy * G + cx + r];
                    pe1 = g_cellstart[vy * G + cx + r + 1];
                }
            }
#pragma unroll
            for (int seg = 0; seg < 2; ++seg) {
                const int ps = seg ? ps1 : ps0;
                const int pe = seg ? pe1 : pe0;
                for (int p0 = ps; p0 < pe; p0 += 32) {
                    const int p = p0 + lane;
                    float d2 = FLT_MAX;
                    if (p < pe && p != s) {
                        const float2 f = g_pts[p];
                        const float dx = q.x - f.x;
                        const float dy = q.y - f.y;
                        d2 = fmaf(dx, dx, dy * dy);
                    }
                    unsigned int m = __ballot_sync(0xffffffffu, d2 < maxv);
                    while (m) {
                        const int l = __ffs(m) - 1;
                        m &= m - 1;
                        const float dd = __shfl_sync(0xffffffffu, d2, l);
                        if (dd < maxv) {
                            const int pp = __shfl_sync(0xffffffffu, p, l);
                            const unsigned int own =
                                __ballot_sync(0xffffffffu, slotval == maxv);
                            const int ol = __ffs(own) - 1;
                            if (lane == ol) { slotval = dd; slotid = pp; }
                            float mx = slotval;
#pragma unroll
                            for (int o = 16; o > 0; o >>= 1)
                                mx = fmaxf(mx, __shfl_xor_sync(0xffffffffu, mx, o));
                            maxv = mx;
                        }
                    }
                }
            }
        }
        if (maxv < FLT_MAX) {
            const float bl = (cx - r > 0)     ? q.x - (xmin + (float)(cx - r) * wx)     : FLT_MAX;
            const float br = (cx + r < G - 1) ? (xmin + (float)(cx + r + 1) * wx) - q.x : FLT_MAX;
            const float bb = (cy - r > 0)     ? q.y - (ymin + (float)(cy - r) * wy)     : FLT_MAX;
            const float bt = (cy + r < G - 1) ? (ymin + (float)(cy + r + 1) * wy) - q.y : FLT_MAX;
            const float b = fminf(fminf(bl, br), fminf(bb, bt));
            if (b == FLT_MAX || (b > 0.0f && b * b > maxv)) break;
        }
    }

    float invd = 0.0f;
    int oid = 0;
    if (lane < KNB) {
        const float2 f = g_pts[slotid];
        oid = g_sidx[slotid];
        const float xi = q.x, yi = q.y;
        const float sqi = __fadd_rn(__fmul_rn(xi, xi), __fmul_rn(yi, yi));
        const float sqj = __fadd_rn(__fmul_rn(f.x, f.x), __fmul_rn(f.y, f.y));
        const float dot = __fadd_rn(__fmul_rn(xi, f.x), __fmul_rn(yi, f.y));
        const float d2  = __fsub_rn(__fadd_rn(sqi, sqj), __fmul_rn(2.0f, dot));
        const float dist = sqrtf(fmaxf(d2, 0.0f));
        invd = 1.0f / fmaxf(dist, 1e-4f);
    }
    float tot = invd;
#pragma unroll
    for (int o = 16; o > 0; o >>= 1)
        tot += __shfl_xor_sync(0xffffffffu, tot, o);
    if (lane < KNB) {
        nidx[i * KNB + lane] = oid;
        nw  [i * KNB + lane] = invd / fmaxf(tot, 1e-8f);
    }
}

// ================= weight split (ranged) =======================================
__global__ void split_w_kernel(const float* __restrict__ w0, const float* __restrict__ w1,
                               const float* __restrict__ w2, const float* __restrict__ w3,
                               const float* __restrict__ w4, const float* __restrict__ w5,
                               int lo, int hi) {
    const int i = lo + blockIdx.x * blockDim.x + threadIdx.x;
    if (i >= hi) return;
    float x;
    if      (i < 65536)  x = w0[i];
    else if (i < 131072) x = w1[i - 65536];
    else if (i < 196608) x = w2[i - 131072];
    else if (i < 262144) x = w3[i - 196608];
    else if (i < 327680) x = w4[i - 262144];
    else                 x = w5[i - 327680];
    const __nv_bfloat16 h = __float2bfloat16(x);
    g_wh[i] = h;
    g_wl[i] = __float2bfloat16(x - __bfloat162float(h));
}

// ================= HMMA GEMM: 64 x 128 tiles, occupancy 3 =====================
// 3-term bf16 split. 8 warps (2m x 4n); per-warp 32 x 32 via 2 x 4 m16n8k16 frags.
// gridDim.y = N-tiles. DUAL: 16 K-chunks in one pass.
// MODE: 0=ENC (bias+gelu -> h + splits), 2=CLS (bias+gelu+dot(w2)+sigmoid -> out),
// 3=SAGE pre-LN (gelu -> tmp fp32).
#define SPAD 40
#define NCOLS 128
template <int MODE, bool DUAL, bool CONVA>
__global__ __launch_bounds__(256, 3) void hmma_gemm_kernel(
    const __nv_bfloat16* __restrict__ a1h, const __nv_bfloat16* __restrict__ a1l,
    const float* __restrict__ a1f,
    const __nv_bfloat16* __restrict__ w1h, const __nv_bfloat16* __restrict__ w1l,
    const __nv_bfloat16* __restrict__ a2h, const __nv_bfloat16* __restrict__ a2l,
    const __nv_bfloat16* __restrict__ w2h, const __nv_bfloat16* __restrict__ w2l,
    const float* __restrict__ bias,
    const float* __restrict__ cw2, const float* __restrict__ cb2,
    float* __restrict__ outS,
    float* outF,
    __nv_bfloat16* __restrict__ outH, __nv_bfloat16* __restrict__ outL, int M) {
    extern __shared__ __nv_bfloat16 smem[];
    __shared__ float red[64][4];

    constexpr int SA = 64 * SPAD;
    constexpr int SB = NCOLS * SPAD;
    constexpr int SST = 2 * SA + 2 * SB;
    constexpr int NJ = NCOLS / 32;     // 4
    constexpr int NJP = NJ / 2;        // 2

    const int tid  = threadIdx.x;
    const int wid  = tid >> 5;
    const int lane = tid & 31;
    const int gid  = lane >> 2;
    const int tig  = lane & 3;
    const int m0 = blockIdx.x * 64;
    const int n0 = blockIdx.y * NCOLS;
    const int mw = (wid >> 2) * 32;
    const int nw = (wid & 3) * (NCOLS / 4);
    const int nchunks = DUAL ? 16 : 8;

    const uint32_t aLane = (uint32_t)(((mw + (lane & 15)) * SPAD + ((lane >> 4) & 1) * 8) * 2);
    const uint32_t bLane = (uint32_t)(((nw + 8 * ((lane >> 4) & 1) + (lane & 7)) * SPAD +
                                       ((lane >> 3) & 1) * 8) * 2);

    float acc[2][NJ][4];
#pragma unroll
    for (int a = 0; a < 2; ++a)
#pragma unroll
        for (int b = 0; b < NJ; ++b)
#pragma unroll
            for (int c = 0; c < 4; ++c) acc[a][b][c] = 0.0f;

    auto stage = [&](int c) {
        const int k0 = (c & 7) * 32;
        const bool s1 = DUAL && (c >= 8);
        const __nv_bfloat16* Ah = s1 ? a2h : a1h;
        const __nv_bfloat16* Al = s1 ? a2l : a1l;
        const __nv_bfloat16* Wh = s1 ? w2h : w1h;
        const __nv_bfloat16* Wl = s1 ? w2l : w1l;
        __nv_bfloat16* buf = smem + (c & 1) * SST;
        __nv_bfloat16* bAh = buf;
        __nv_bfloat16* bAl = buf + SA;
        __nv_bfloat16* bBh = buf + 2 * SA;
        __nv_bfloat16* bBl = buf + 2 * SA + SB;
        {   // A tile: 64 rows x 32, one 16B item per thread
            const int r = tid >> 2, qd = tid & 3;
            const int off = r * SPAD + qd * 8;
            if (CONVA) {
                const int mg = m0 + r;
                __align__(16) __nv_bfloat16 hh[8], ll[8];
                if (mg < M) {
                    const float* fp = a1f + (size_t)mg * HID + k0 + qd * 8;
                    const float4 f0 = *reinterpret_cast<const float4*>(fp);
                    const float4 f1 = *reinterpret_cast<const float4*>(fp + 4);
                    const float fv[8] = {f0.x, f0.y, f0.z, f0.w, f1.x, f1.y, f1.z, f1.w};
#pragma unroll
                    for (int j = 0; j < 8; ++j) {
                        hh[j] = __float2bfloat16(fv[j]);
                        ll[j] = __float2bfloat16(fv[j] - __bfloat162float(hh[j]));
                    }
                } else {
#pragma unroll
                    for (int j = 0; j < 8; ++j) { hh[j] = __nv_bfloat16(0.f); ll[j] = __nv_bfloat16(0.f); }
                }
                *reinterpret_cast<uint4*>(bAh + off) = *reinterpret_cast<const uint4*>(hh);
                *reinterpret_cast<uint4*>(bAl + off) = *reinterpret_cast<const uint4*>(ll);
            } else {
                cpa16(bAh + off, Ah + (size_t)(m0 + r) * HID + k0 + qd * 8);
                cpa16(bAl + off, Al + (size_t)(m0 + r) * HID + k0 + qd * 8);
            }
        }
        // B tile: NCOLS rows x 32: NCOLS*4 = 512 items / 256 threads = 2 each
#pragma unroll
        for (int u = tid; u < NCOLS * 4; u += 256) {
            const int r = u >> 2, qd = u & 3;
            const int off = r * SPAD + qd * 8;
            cpa16(bBh + off, Wh + (size_t)(n0 + r) * HID + k0 + qd * 8);
            cpa16(bBl + off, Wl + (size_t)(n0 + r) * HID + k0 + qd * 8);
        }
        asm volatile("cp.async.commit_group;" ::: "memory");
    };

    stage(0);
    for (int c = 0; c < nchunks; ++c) {
        if (c + 1 < nchunks) {
            stage(c + 1);
            asm volatile("cp.async.wait_group 1;" ::: "memory");
        } else {
            asm volatile("cp.async.wait_group 0;" ::: "memory");
        }
        __syncthreads();

        const uint32_t bufB = smem_u32(smem + (c & 1) * SST);
        const uint32_t aH = bufB + aLane;
        const uint32_t aL = bufB + SA * 2 + aLane;
        const uint32_t bH = bufB + 2 * SA * 2 + bLane;
        const uint32_t bL = bufB + (2 * SA + SB) * 2 + bLane;

#pragma unroll
        for (int kk = 0; kk < 32; kk += 16) {
            uint32_t afh[2][4], afl[2][4];
#pragma unroll
            for (int mi = 0; mi < 2; ++mi) {
                ldsm_x4(afh[mi], aH + (uint32_t)(mi * 32 * SPAD + 2 * kk));
                ldsm_x4(afl[mi], aL + (uint32_t)(mi * 32 * SPAD + 2 * kk));
            }
#pragma unroll
            for (int njp = 0; njp < NJP; ++njp) {
                uint32_t bh[4], bl[4];
                ldsm_x4(bh, bH + (uint32_t)(njp * 32 * SPAD + 2 * kk));
                ldsm_x4(bl, bL + (uint32_t)(njp * 32 * SPAD + 2 * kk));
#pragma unroll
                for (int mi = 0; mi < 2; ++mi) {
                    mma16816(acc[mi][2 * njp],     afh[mi], bh);
                    mma16816(acc[mi][2 * njp],     afh[mi], bl);
                    mma16816(acc[mi][2 * njp],     afl[mi], bh);
                    mma16816(acc[mi][2 * njp + 1], afh[mi], bh + 2);
                    mma16816(acc[mi][2 * njp + 1], afh[mi], bl + 2);
                    mma16816(acc[mi][2 * njp + 1], afl[mi], bh + 2);
                }
            }
        }
        __syncthreads();
    }

    // ---- epilogue: bias (MODE 0/2) + gelu (all) ----
#pragma unroll
    for (int mi = 0; mi < 2; ++mi)
#pragma unroll
        for (int nj = 0; nj < NJ; ++nj)
#pragma unroll
            for (int q = 0; q < 4; ++q) {
                float v = acc[mi][nj][q];
                if (MODE == 0 || MODE == 2) v += bias[n0 + nw + 8 * nj + tig * 2 + (q & 1)];
                acc[mi][nj][q] = gelu_f(v);
            }

    if (MODE == 3) {          // SAGE pre-LN: gelu -> tmp (fp32, stride HID)
#pragma unroll
        for (int mi = 0; mi < 2; ++mi)
#pragma unroll
            for (int half = 0; half < 2; ++half) {
                const int m = m0 + mw + 16 * mi + gid + 8 * half;
                if (m >= M) continue;
#pragma unroll
                for (int nj = 0; nj < NJ; ++nj) {
                    const int ng = n0 + nw + 8 * nj + tig * 2;
                    *reinterpret_cast<float2*>(outF + (size_t)m * HID + ng) =
                        make_float2(acc[mi][nj][2 * half], acc[mi][nj][2 * half + 1]);
                }
            }
    } else if (MODE == 0) {   // ENC: h + splits
#pragma unroll
        for (int mi = 0; mi < 2; ++mi)
#pragma unroll
            for (int half = 0; half < 2; ++half) {
                const int m = m0 + mw + 16 * mi + gid + 8 * half;
                if (m >= M) continue;
#pragma unroll
                for (int nj = 0; nj < NJ; ++nj) {
                    const int ng = n0 + nw + 8 * nj + tig * 2;
                    const float v0 = acc[mi][nj][2 * half];
                    const float v1 = acc[mi][nj][2 * half + 1];
                    *reinterpret_cast<float2*>(outF + (size_t)m * HID + ng) =
                        make_float2(v0, v1);
                    __nv_bfloat162 hv, lv;
                    hv.x = __float2bfloat16(v0); hv.y = __float2bfloat16(v1);
                    lv.x = __float2bfloat16(v0 - __bfloat162float(hv.x));
                    lv.y = __float2bfloat16(v1 - __bfloat162float(hv.y));
                    *reinterpret_cast<__nv_bfloat162*>(&outH[(size_t)m * HID + ng]) = hv;
                    *reinterpret_cast<__nv_bfloat162*>(&outL[(size_t)m * HID + ng]) = lv;
                }
            }
    } else {                  // MODE 2: CLS — dot with w2 + sigmoid (n0 == 0)
#pragma unroll
        for (int mi = 0; mi < 2; ++mi)
#pragma unroll
            for (int half = 0; half < 2; ++half) {
                float d = 0.0f;
#pragma unroll
                for (int nj = 0; nj < NJ; ++nj) {
                    const int ng = nw + 8 * nj + tig * 2;
                    d = fmaf(acc[mi][nj][2 * half], cw2[ng],
                        fmaf(acc[mi][nj][2 * half + 1], cw2[ng + 1], d));
                }
                d += __shfl_xor_sync(0xffffffffu, d, 1);
                d += __shfl_xor_sync(0xffffffffu, d, 2);
                if (tig == 0) {
                    const int rl = mw + 16 * mi + gid + 8 * half;
                    red[rl][wid & 3] = d;
                }
            }
        __syncthreads();
        if ((wid & 3) == 0 && tig == 0) {
#pragma unroll
            for (int mi = 0; mi < 2; ++mi)
#pragma unroll
                for (int half = 0; half < 2; ++half) {
                    const int rl = mw + 16 * mi + gid + 8 * half;
                    const int m = m0 + rl;
                    if (m >= M) continue;
                    const float logit = red[rl][0] + red[rl][1] +
                                        red[rl][2] + red[rl][3] + cb2[0];
                    outS[m] = 1.0f / (1.0f + expf(-logit));
                }
        }
    }
}

// ================= layernorm + residual (reads tmp; emits h + bf16 split) =====
__global__ void ln_res_kernel(const float* __restrict__ x, const float* __restrict__ g,
                              const float* __restrict__ b, float* __restrict__ h,
                              __nv_bfloat16* __restrict__ ah, __nv_bfloat16* __restrict__ al) {
    const int n = blockIdx.x;
    const int d = threadIdx.x;
    __shared__ float red[8];
    __shared__ float s_mu, s_rstd;

    const float v = x[(size_t)n * HID + d];
    float s = v;
#pragma unroll
    for (int o = 16; o > 0; o >>= 1) s += __shfl_xor_sync(0xffffffffu, s, o);
    if ((d & 31) == 0) red[d >> 5] = s;
    __syncthreads();
    if (d == 0) {
        float t = 0.0f;
        for (int i = 0; i < 8; ++i) t += red[i];
        s_mu = t * (1.0f / HID);
    }
    __syncthreads();
    const float mu = s_mu;
    const float df = v - mu;
    float q = df * df;
#pragma unroll
    for (int o = 16; o > 0; o >>= 1) q += __shfl_xor_sync(0xffffffffu, q, o);
    __syncthreads();
    if ((d & 31) == 0) red[d >> 5] = q;
    __syncthreads();
    if (d == 0) {
        float t = 0.0f;
        for (int i = 0; i < 8; ++i) t += red[i];
        s_rstd = rsqrtf(t * (1.0f / HID) + 1e-5f);
    }
    __syncthreads();
    const float hv = h[(size_t)n * HID + d] + df * s_rstd * g[d] + b[d];
    h[(size_t)n * HID + d] = hv;
    const __nv_bfloat16 hi = __float2bfloat16(hv);
    ah[(size_t)n * HID + d] = hi;
    al[(size_t)n * HID + d] = __float2bfloat16(hv - __bfloat162float(hi));
}

// ================= neighbor aggregation (emits bf16 split) ====================
__global__ void agg_kernel(const float* __restrict__ h, const int* __restrict__ nidx,
                           const float* __restrict__ nw,
                           __nv_bfloat16* __restrict__ gh, __nv_bfloat16* __restrict__ gl) {
    const int n = blockIdx.x;
    const int d = threadIdx.x;
    __shared__ int   sidx[KNB];
    __shared__ float sw  [KNB];
    if (d < KNB) { sidx[d] = nidx[n * KNB + d]; sw[d] = nw[n * KNB + d]; }
    __syncthreads();
    float acc = 0.0f;
#pragma unroll
    for (int k = 0; k < KNB; ++k)
        acc = fmaf(sw[k], h[(size_t)sidx[k] * HID + d], acc);
    const __nv_bfloat16 hi = __float2bfloat16(acc);
    gh[(size_t)n * HID + d] = hi;
    gl[(size_t)n * HID + d] = __float2bfloat16(acc - __bfloat162float(hi));
}

// ================= launch =======================================================
extern "C" void kernel_launch(void* const* d_in, const int* in_sizes, int n_in,
                              void* d_out, int out_size) {
    const float* feats  = (const float*)d_in[0];
    const float* cents  = (const float*)d_in[1];
    const float* enc_w  = (const float*)d_in[2];
    const float* enc_b  = (const float*)d_in[3];
    const float* g1_ws  = (const float*)d_in[4];
    const float* g1_wn  = (const float*)d_in[5];
    const float* g1_g   = (const float*)d_in[6];
    const float* g1_b   = (const float*)d_in[7];
    const float* g2_ws  = (const float*)d_in[8];
    const float* g2_wn  = (const float*)d_in[9];
    const float* g2_g   = (const float*)d_in[10];
    const float* g2_b   = (const float*)d_in[11];
    const float* cls_w1 = (const float*)d_in[12];
    const float* cls_b1 = (const float*)d_in[13];
    const float* cls_w2 = (const float*)d_in[14];
    const float* cls_b2 = (const float*)d_in[15];
    float* out = (float*)d_out;

    float *p_h, *p_tmp, *p_nw;
    int* p_nidx;
    __nv_bfloat16 *p_ah, *p_al, *p_gh, *p_gl, *p_wh, *p_wl;
    cudaGetSymbolAddress((void**)&p_h,    g_h);
    cudaGetSymbolAddress((void**)&p_tmp,  g_tmp);
    cudaGetSymbolAddress((void**)&p_nidx, g_nidx);
    cudaGetSymbolAddress((void**)&p_nw,   g_nw);
    cudaGetSymbolAddress((void**)&p_ah,   g_ah);
    cudaGetSymbolAddress((void**)&p_al,   g_al);
    cudaGetSymbolAddress((void**)&p_gh,   g_gh);
    cudaGetSymbolAddress((void**)&p_gl,   g_gl);
    cudaGetSymbolAddress((void**)&p_wh,   g_wh);
    cudaGetSymbolAddress((void**)&p_wl,   g_wl);

    const int M = NPTS;
    const int NBLK = (M + 63) / 64;   // 188
    const int SMEM = (2 * (2 * 64 * SPAD + 2 * NCOLS * SPAD)) * (int)sizeof(__nv_bfloat16); // 61440

    cudaFuncSetAttribute(hmma_gemm_kernel<0, false, true >,
                         cudaFuncAttributeMaxDynamicSharedMemorySize, SMEM);
    cudaFuncSetAttribute(hmma_gemm_kernel<3, true,  false>,
                         cudaFuncAttributeMaxDynamicSharedMemorySize, SMEM);
    cudaFuncSetAttribute(hmma_gemm_kernel<2, false, false>,
                         cudaFuncAttributeMaxDynamicSharedMemorySize, SMEM);

    cudaStream_t s2;
    cudaStreamCreateWithFlags(&s2, cudaStreamNonBlocking);
    cudaEvent_t evF, evJ;
    cudaEventCreateWithFlags(&evF, cudaEventDisableTiming);
    cudaEventCreateWithFlags(&evJ, cudaEventDisableTiming);
    cudaEventRecord(evF, 0);
    cudaStreamWaitEvent(s2, evF, 0);

    const dim3 gFull(NBLK, 2);   // 376 tiles
    const dim3 gCls(NBLK, 1);

    // ---- s2: KNN (fused build + fast query) ----
    knn_build_kernel<<<1, 1024, 0, s2>>>(cents);
    knn_query_kernel<<<(NPTS * 32 + 255) / 256, 256, 0, s2>>>(p_nidx, p_nw);
    cudaEventRecord(evJ, s2);

    // ---- main: encoder-slice split -> encoder -> remaining splits in slack ----
    split_w_kernel<<<(WENC + 255) / 256, 256>>>(
        enc_w, g1_ws, g1_wn, g2_ws, g2_wn, cls_w1, 0, WENC);
    hmma_gemm_kernel<0, false, true><<<gFull, 256, SMEM>>>(
        nullptr, nullptr, feats, p_wh + 0, p_wl + 0,
        nullptr, nullptr, nullptr, nullptr,
        enc_b, nullptr, nullptr, nullptr,
        p_h, p_ah, p_al, M);
    split_w_kernel<<<(WTOT - WENC + 255) / 256, 256>>>(
        enc_w, g1_ws, g1_wn, g2_ws, g2_wn, cls_w1, WENC, WTOT);

    // join: agg needs knn graph + h
    cudaStreamWaitEvent(0, evJ, 0);

    // ---- SAGE layer 1 ----
    agg_kernel<<<NPTS, HID>>>(p_h, p_nidx, p_nw, p_gh, p_gl);
    hmma_gemm_kernel<3, true, false><<<gFull, 256, SMEM>>>(
        p_ah, p_al, nullptr, p_wh + 65536, p_wl + 65536,
        p_gh, p_gl, p_wh + 131072, p_wl + 131072,
        nullptr, nullptr, nullptr, nullptr,
        p_tmp, nullptr, nullptr, M);
    ln_res_kernel<<<NPTS, HID>>>(p_tmp, g1_g, g1_b, p_h, p_ah, p_al);

    // ---- SAGE layer 2 ----
    agg_kernel<<<NPTS, HID>>>(p_h, p_nidx, p_nw, p_gh, p_gl);
    hmma_gemm_kernel<3, true, false><<<gFull, 256, SMEM>>>(
        p_ah, p_al, nullptr, p_wh + 196608, p_wl + 196608,
        p_gh, p_gl, p_wh + 262144, p_wl + 262144,
        nullptr, nullptr, nullptr, nullptr,
        p_tmp, nullptr, nullptr, M);
    ln_res_kernel<<<NPTS, HID>>>(p_tmp, g2_g, g2_b, p_h, p_ah, p_al);

    // ---- classifier (fused dot + sigmoid) ----
    hmma_gemm_kernel<2, false, false><<<gCls, 256, SMEM>>>(
        p_ah, p_al, nullptr, p_wh + 327680, p_wl + 327680,
        nullptr, nullptr, nullptr, nullptr,
        cls_b1, cls_w2, cls_b2, out,
        nullptr, nullptr, nullptr, M);
}

// round 16
// speedup vs baseline: 1.6040x; 1.1191x over previous
#include <cuda_runtime.h>
#include <cuda_bf16.h>
#include <cstdint>
#include <cfloat>
#include <math.h>

#define NPTS 12000
#define MPAD 12032
#define HID  256
#define KNB  16
#define G    64
#define NCELL (G * G)

// ---------------- scratch (allocation-free: __device__ globals) --------------
__device__ float g_h   [MPAD * HID];
__device__ float g_tmp [MPAD * HID];
__device__ int   g_nidx[NPTS * KNB];
__device__ float g_nw  [NPTS * KNB];

// blocked bf16 split operand buffers (tile/chunk blocked, swizzled)
__device__ __nv_bfloat16 g_ah[MPAD * HID], g_al[MPAD * HID];   // h split
__device__ __nv_bfloat16 g_gh[MPAD * HID], g_gl[MPAD * HID];   // agg split
#define WTOT 360448
#define WENC 65536
__device__ __nv_bfloat16 g_wh[WTOT], g_wl[WTOT];
// slots: enc=0, g1ws=65536, g1wn=131072, g2ws=196608, g2wn=262144, cls=327680

// grid-knn scratch
__device__ unsigned int g_bbox[4];
__device__ int    g_cellstart[NCELL + 1];
__device__ float2 g_pts [NPTS];
__device__ int    g_sidx[NPTS];

__device__ __forceinline__ float gelu_f(float x) {
    return 0.5f * x * (1.0f + erff(x * 0.70710678118654752440f));
}

__device__ __forceinline__ unsigned int fenc(float f) {
    unsigned int u = __float_as_uint(f);
    return (u & 0x80000000u) ? ~u : (u | 0x80000000u);
}
__device__ __forceinline__ float fdec(unsigned int u) {
    return __uint_as_float((u & 0x80000000u) ? (u ^ 0x80000000u) : ~u);
}

__device__ __forceinline__ uint32_t smem_u32(const void* p) {
    uint32_t a;
    asm("{ .reg .u64 t; cvta.to.shared.u64 t, %1; cvt.u32.u64 %0, t; }" : "=r"(a) : "l"(p));
    return a;
}
__device__ __forceinline__ void ldsm_x4(uint32_t* r, uint32_t addr) {
    asm volatile("ldmatrix.sync.aligned.m8n8.x4.shared.b16 {%0,%1,%2,%3}, [%4];"
                 : "=r"(r[0]), "=r"(r[1]), "=r"(r[2]), "=r"(r[3]) : "r"(addr));
}
__device__ __forceinline__ void bulk_cp(uint32_t dst, const void* src, uint32_t bytes,
                                        uint32_t mbar) {
    asm volatile(
        "cp.async.bulk.shared::cta.global.mbarrier::complete_tx::bytes [%0], [%1], %2, [%3];"
        :: "r"(dst), "l"(src), "r"(bytes), "r"(mbar) : "memory");
}
#define MBAR_INIT(mb, c) \
    asm volatile("mbarrier.init.shared.b64 [%0], %1;" :: "r"((uint32_t)(mb)), "r"((uint32_t)(c)) : "memory")
#define MBAR_EXPECT(mb, tx) \
    asm volatile("mbarrier.arrive.expect_tx.shared.b64 _, [%0], %1;" \
                 :: "r"((uint32_t)(mb)), "r"((uint32_t)(tx)) : "memory")
__device__ __forceinline__ void mbar_wait(uint32_t mb, uint32_t parity) {
    asm volatile(
        "{\n\t.reg .pred P;\n\t"
        "W_%=:\n\t"
        "mbarrier.try_wait.parity.acquire.cta.shared::cta.b64 P, [%0], %1, 0x989680;\n\t"
        "@!P bra.uni W_%=;\n\t"
        "}" :: "r"(mb), "r"(parity) : "memory");
}

// HMMA: D(f32) += A(bf16,row) * B(bf16,col), m16n8k16
__device__ __forceinline__ void mma16816(float* c, const uint32_t* a, const uint32_t* b) {
    asm volatile(
        "mma.sync.aligned.m16n8k16.row.col.f32.bf16.bf16.f32 "
        "{%0,%1,%2,%3}, {%4,%5,%6,%7}, {%8,%9}, {%0,%1,%2,%3};"
        : "+f"(c[0]), "+f"(c[1]), "+f"(c[2]), "+f"(c[3])
        : "r"(a[0]), "r"(a[1]), "r"(a[2]), "r"(a[3]), "r"(b[0]), "r"(b[1]));
}

// blocked+swizzled layouts.
// A (activations): 64-row tiles, 32-K chunks: block = 2048 elems.
__device__ __forceinline__ int boffA(int m, int d) {
    return ((m >> 6) << 14) | ((d >> 5) << 11) | ((m & 63) << 5) |
           ((((d >> 3) + m + (m >> 2)) & 3) << 3) | (d & 7);
}
// B (weights): 128-row tiles, 32-K chunks: block = 4096 elems.
__device__ __forceinline__ int boffB(int n, int k) {
    return ((n >> 7) << 15) | ((k >> 5) << 12) | ((n & 127) << 5) |
           ((((k >> 3) + n + (n >> 2)) & 3) << 3) | (k & 7);
}

// ================= KNN build: ONE CTA does bbox+count+scan+scatter =============
__global__ __launch_bounds__(1024) void knn_build_kernel(const float* __restrict__ cents) {
    __shared__ int   scnt[NCELL];
    __shared__ float rmnx[32], rmxx[32], rmny[32], rmxy[32];
    __shared__ float sbb[4];
    __shared__ int   wsum[32];
    const int t = threadIdx.x;
    const int lane = t & 31;
    const int warp = t >> 5;

    float2 pts[12];
    int np = 0;
    for (int i = t; i < NPTS; i += 1024) pts[np++] = *reinterpret_cast<const float2*>(cents + 2 * i);

    float xmn = FLT_MAX, xmx = -FLT_MAX, ymn = FLT_MAX, ymx = -FLT_MAX;
    for (int j = 0; j < np; ++j) {
        xmn = fminf(xmn, pts[j].x); xmx = fmaxf(xmx, pts[j].x);
        ymn = fminf(ymn, pts[j].y); ymx = fmaxf(ymx, pts[j].y);
    }
#pragma unroll
    for (int o = 16; o > 0; o >>= 1) {
        xmn = fminf(xmn, __shfl_xor_sync(0xffffffffu, xmn, o));
        xmx = fmaxf(xmx, __shfl_xor_sync(0xffffffffu, xmx, o));
        ymn = fminf(ymn, __shfl_xor_sync(0xffffffffu, ymn, o));
        ymx = fmaxf(ymx, __shfl_xor_sync(0xffffffffu, ymx, o));
    }
    if (lane == 0) { rmnx[warp] = xmn; rmxx[warp] = xmx; rmny[warp] = ymn; rmxy[warp] = ymx; }
    __syncthreads();
    if (t == 0) {
        float a = rmnx[0], b = rmxx[0], c = rmny[0], d = rmxy[0];
        for (int i = 1; i < 32; ++i) {
            a = fminf(a, rmnx[i]); b = fmaxf(b, rmxx[i]);
            c = fminf(c, rmny[i]); d = fmaxf(d, rmxy[i]);
        }
        sbb[0] = a; sbb[1] = b; sbb[2] = c; sbb[3] = d;
        g_bbox[0] = fenc(a); g_bbox[1] = fenc(b);
        g_bbox[2] = fenc(c); g_bbox[3] = fenc(d);
    }
    for (int c = t; c < NCELL; c += 1024) scnt[c] = 0;
    __syncthreads();

    const float xmin = sbb[0], ymin = sbb[2];
    const float rx = fmaxf(sbb[1] - xmin, 1e-20f);
    const float ry = fmaxf(sbb[3] - ymin, 1e-20f);
    const float iwx = (float)G / rx, iwy = (float)G / ry;

    int cellid[12];
    for (int j = 0; j < np; ++j) {
        int cx = (int)((pts[j].x - xmin) * iwx); cx = min(max(cx, 0), G - 1);
        int cy = (int)((pts[j].y - ymin) * iwy); cy = min(max(cy, 0), G - 1);
        cellid[j] = cy * G + cx;
        atomicAdd(&scnt[cellid[j]], 1);
    }
    __syncthreads();

    const int base = t * 4;
    int loc[4];
    int s = 0;
#pragma unroll
    for (int j = 0; j < 4; ++j) { loc[j] = s; s += scnt[base + j]; }
    int v = s;
#pragma unroll
    for (int o = 1; o < 32; o <<= 1) {
        const int n = __shfl_up_sync(0xffffffffu, v, o);
        if (lane >= o) v += n;
    }
    if (lane == 31) wsum[warp] = v;
    __syncthreads();
    if (t == 0) {
        int run = 0;
        for (int i = 0; i < 32; ++i) { const int tmp = wsum[i]; wsum[i] = run; run += tmp; }
    }
    __syncthreads();
    const int pre = wsum[warp] + (v - s);
#pragma unroll
    for (int j = 0; j < 4; ++j) loc[j] += pre;
#pragma unroll
    for (int j = 0; j < 4; ++j) g_cellstart[base + j] = loc[j];
    if (t == 1023) g_cellstart[NCELL] = NPTS;
    __syncthreads();
#pragma unroll
    for (int j = 0; j < 4; ++j) scnt[base + j] = loc[j];
    __syncthreads();

    for (int j = 0; j < np; ++j) {
        const int slot = atomicAdd(&scnt[cellid[j]], 1);
        g_pts [slot] = pts[j];
        g_sidx[slot] = t + 1024 * j;
    }
}

__device__ __forceinline__ void grid_params(float& xmin, float& ymin,
                                            float& iwx, float& iwy,
                                            float& wx, float& wy) {
    xmin = fdec(g_bbox[0]);
    const float xmax = fdec(g_bbox[1]);
    ymin = fdec(g_bbox[2]);
    const float ymax = fdec(g_bbox[3]);
    const float rx = fmaxf(xmax - xmin, 1e-20f);
    const float ry = fmaxf(ymax - ymin, 1e-20f);
    iwx = (float)G / rx; iwy = (float)G / ry;
    wx = rx / (float)G;  wy = ry / (float)G;
}

__device__ __forceinline__ int cell_x(float x, float xmin, float iwx) {
    int c = (int)((x - xmin) * iwx);
    return min(max(c, 0), G - 1);
}

// ================= KNN query: warp/query, LANE-DISTRIBUTED shared top-16 ======
__global__ void knn_query_kernel(int* __restrict__ nidx, float* __restrict__ nw) {
    const int w = (blockIdx.x * blockDim.x + threadIdx.x) >> 5;
    const int lane = threadIdx.x & 31;
    if (w >= NPTS) return;
    const int s = w;
    const float2 q = g_pts[s];
    const int i = g_sidx[s];

    float xmin, ymin, iwx, iwy, wx, wy;
    grid_params(xmin, ymin, iwx, iwy, wx, wy);
    const int cx = cell_x(q.x, xmin, iwx);
    const int cy = cell_x(q.y, ymin, iwy);

    float slotval = (lane < KNB) ? FLT_MAX : -FLT_MAX;
    int   slotid  = 0;
    float maxv = FLT_MAX;

    for (int r = 0; r < G; ++r) {
        const int ylo = max(cy - r, 0), yhi = min(cy + r, G - 1);
        for (int vy = ylo; vy <= yhi; ++vy) {
            const bool edge_row = (vy == cy - r) || (vy == cy + r);
            int ps0 = 0, pe0 = 0, ps1 = 0, pe1 = 0;
            if (edge_row) {
                const int xl = max(cx - r, 0), xh = min(cx + r, G - 1);
                ps0 = g_cellstart[vy * G + xl];
                pe0 = g_cellstart[vy * G + xh + 1];
            } else {
                if (cx - r >= 0) {
                    ps0 = g_cellstart[vy * G + cx - r];
                    pe0 = g_cellstart[vy * G + cx - r + 1];
                }
                if (cx + r <= G - 1) {
                    ps1 = g_cellstart[vy * G + cx + r];
                    pe1 = g_cellstart[vy * G + cx + r + 1];
                }
            }
#pragma unroll
            for (int seg = 0; seg < 2; ++seg) {
                const int ps = seg ? ps1 : ps0;
                const int pe = seg ? pe1 : pe0;
                for (int p0 = ps; p0 < pe; p0 += 32) {
                    const int p = p0 + lane;
                    float d2 = FLT_MAX;
                    if (p < pe && p != s) {
                        const float2 f = g_pts[p];
                        const float dx = q.x - f.x;
                        const float dy = q.y - f.y;
                        d2 = fmaf(dx, dx, dy * dy);
                    }
                    unsigned int m = __ballot_sync(0xffffffffu, d2 < maxv);
                    while (m) {
                        const int l = __ffs(m) - 1;
                        m &= m - 1;
                        const float dd = __shfl_sync(0xffffffffu, d2, l);
                        if (dd < maxv) {
                            const int pp = __shfl_sync(0xffffffffu, p, l);
                            const unsigned int own =
                                __ballot_sync(0xffffffffu, slotval == maxv);
                            const int ol = __ffs(own) - 1;
                            if (lane == ol) { slotval = dd; slotid = pp; }
                            float mx = slotval;
#pragma unroll
                            for (int o = 16; o > 0; o >>= 1)
                                mx = fmaxf(mx, __shfl_xor_sync(0xffffffffu, mx, o));
                            maxv = mx;
                        }
                    }
                }
            }
        }
        if (maxv < FLT_MAX) {
            const float bl = (cx - r > 0)     ? q.x - (xmin + (float)(cx - r) * wx)     : FLT_MAX;
            const float br = (cx + r < G - 1) ? (xmin + (float)(cx + r + 1) * wx) - q.x : FLT_MAX;
            const float bb = (cy - r > 0)     ? q.y - (ymin + (float)(cy - r) * wy)     : FLT_MAX;
            const float bt = (cy + r < G - 1) ? (ymin + (float)(cy + r + 1) * wy) - q.y : FLT_MAX;
            const float b = fminf(fminf(bl, br), fminf(bb, bt));
            if (b == FLT_MAX || (b > 0.0f && b * b > maxv)) break;
        }
    }

    float invd = 0.0f;
    int oid = 0;
    if (lane < KNB) {
        const float2 f = g_pts[slotid];
        oid = g_sidx[slotid];
        const float xi = q.x, yi = q.y;
        const float sqi = __fadd_rn(__fmul_rn(xi, xi), __fmul_rn(yi, yi));
        const float sqj = __fadd_rn(__fmul_rn(f.x, f.x), __fmul_rn(f.y, f.y));
        const float dot = __fadd_rn(__fmul_rn(xi, f.x), __fmul_rn(yi, f.y));
        const float d2  = __fsub_rn(__fadd_rn(sqi, sqj), __fmul_rn(2.0f, dot));
        const float dist = sqrtf(fmaxf(d2, 0.0f));
        invd = 1.0f / fmaxf(dist, 1e-4f);
    }
    float tot = invd;
#pragma unroll
    for (int o = 16; o > 0; o >>= 1)
        tot += __shfl_xor_sync(0xffffffffu, tot, o);
    if (lane < KNB) {
        nidx[i * KNB + lane] = oid;
        nw  [i * KNB + lane] = invd / fmaxf(tot, 1e-8f);
    }
}

// ================= weight split (ranged, writes BLOCKED layout) ================
__global__ void split_w_kernel(const float* __restrict__ w0, const float* __restrict__ w1,
                               const float* __restrict__ w2, const float* __restrict__ w3,
                               const float* __restrict__ w4, const float* __restrict__ w5,
                               int lo, int hi) {
    const int i = lo + blockIdx.x * blockDim.x + threadIdx.x;
    if (i >= hi) return;
    float x;
    int base, r;
    if      (i < 65536)  { x = w0[i];          base = 0;      r = i; }
    else if (i < 131072) { x = w1[i - 65536];  base = 65536;  r = i - 65536; }
    else if (i < 196608) { x = w2[i - 131072]; base = 131072; r = i - 131072; }
    else if (i < 262144) { x = w3[i - 196608]; base = 196608; r = i - 196608; }
    else if (i < 327680) { x = w4[i - 262144]; base = 262144; r = i - 262144; }
    else                 { x = w5[i - 327680]; base = 327680; r = i - 327680; }
    const int n = r >> 8, k = r & 255;
    const int o = base + boffB(n, k);
    const __nv_bfloat16 h = __float2bfloat16(x);
    g_wh[o] = h;
    g_wl[o] = __float2bfloat16(x - __bfloat162float(h));
}

// ================= HMMA GEMM: bulk-copy staged, 64x128 tiles, occ 3 ===========
// 3-term bf16 split. 8 warps (2m x 4n); per-warp 32x32 via 2x4 m16n8k16 frags.
// MODE: 0=ENC (bias+gelu -> h + blocked splits), 2=CLS (bias+gelu+dot+sigmoid),
// 3=SAGE pre-LN (gelu -> tmp fp32). Operands pre-blocked+swizzled in global.
#define NCOLS 128
#define STG_B 24576   // bytes per stage: Ah 4096 | Al 4096 | Bh 8192 | Bl 8192
template <int MODE, bool DUAL, bool CONVA>
__global__ __launch_bounds__(256, 3) void hmma_gemm_kernel(
    const __nv_bfloat16* __restrict__ a1h, const __nv_bfloat16* __restrict__ a1l,
    const float* __restrict__ a1f,
    const __nv_bfloat16* __restrict__ w1h, const __nv_bfloat16* __restrict__ w1l,
    const __nv_bfloat16* __restrict__ a2h, const __nv_bfloat16* __restrict__ a2l,
    const __nv_bfloat16* __restrict__ w2h, const __nv_bfloat16* __restrict__ w2l,
    const float* __restrict__ bias,
    const float* __restrict__ cw2, const float* __restrict__ cb2,
    float* __restrict__ outS,
    float* outF,
    __nv_bfloat16* __restrict__ outH, __nv_bfloat16* __restrict__ outL, int M) {
    extern __shared__ __nv_bfloat16 smem[];
    __shared__ float red[64][4];
    __shared__ __align__(16) unsigned long long mbars[2];

    constexpr int NJ = NCOLS / 32;     // 4
    constexpr int NJP = NJ / 2;        // 2

    const int tid  = threadIdx.x;
    const int wid  = tid >> 5;
    const int lane = tid & 31;
    const int gid  = lane >> 2;
    const int tig  = lane & 3;
    const int m0 = blockIdx.x * 64;
    const int n0 = blockIdx.y * NCOLS;
    const int mw = (wid >> 2) * 32;
    const int nw = (wid & 3) * 32;
    const int nchunks = DUAL ? 16 : 8;

    const uint32_t smemB = smem_u32(smem);
    const uint32_t mb0 = smem_u32(&mbars[0]);
    const uint32_t mb1 = smem_u32(&mbars[1]);

    if (tid == 0) { MBAR_INIT(mb0, 1); MBAR_INIT(mb1, 1); }
    __syncthreads();

    // per-lane ldsm row/group components
    const int rA = mw + (lane & 15);
    const int gA = (lane >> 4) & 1;
    const int rB = nw + 8 * ((lane >> 4) & 1) + (lane & 7);
    const int gB = (lane >> 3) & 1;

    float acc[2][NJ][4];
#pragma unroll
    for (int a = 0; a < 2; ++a)
#pragma unroll
        for (int b = 0; b < NJ; ++b)
#pragma unroll
            for (int c = 0; c < 4; ++c) acc[a][b][c] = 0.0f;

    auto stage = [&](int c) {
        const uint32_t sbW = smemB + (uint32_t)(c & 1) * STG_B;
        if (CONVA) {
            // convert feats fp32 -> hi/lo bf16 directly into swizzled smem
            const int r = tid >> 2, qd = tid & 3;
            const uint32_t off = (uint32_t)(r * 64 + (((qd + r + (r >> 2)) & 3) << 4));
            const int mg = m0 + r;
            __align__(16) __nv_bfloat16 hh[8], ll[8];
            if (mg < M) {
                const float* fp = a1f + (size_t)mg * HID + (c & 7) * 32 + qd * 8;
                const float4 f0 = *reinterpret_cast<const float4*>(fp);
                const float4 f1 = *reinterpret_cast<const float4*>(fp + 4);
                const float fv[8] = {f0.x, f0.y, f0.z, f0.w, f1.x, f1.y, f1.z, f1.w};
#pragma unroll
                for (int j = 0; j < 8; ++j) {
                    hh[j] = __float2bfloat16(fv[j]);
                    ll[j] = __float2bfloat16(fv[j] - __bfloat162float(hh[j]));
                }
            } else {
#pragma unroll
                for (int j = 0; j < 8; ++j) { hh[j] = __nv_bfloat16(0.f); ll[j] = __nv_bfloat16(0.f); }
            }
            *reinterpret_cast<uint4*>(smem + ((sbW - smemB) >> 1) + (off >> 1)) =
                *reinterpret_cast<const uint4*>(hh);
            *reinterpret_cast<uint4*>(smem + ((sbW - smemB) >> 1) + ((off + 4096) >> 1)) =
                *reinterpret_cast<const uint4*>(ll);
        }
        if (tid == 0) {
            const uint32_t mb = (c & 1) ? mb1 : mb0;
            MBAR_EXPECT(mb, CONVA ? 16384u : 24576u);
            const bool s1 = DUAL && (c >= 8);
            const __nv_bfloat16* Wh = s1 ? w2h : w1h;
            const __nv_bfloat16* Wl = s1 ? w2l : w1l;
            const size_t bofs = (size_t)blockIdx.y * 32768 + (size_t)(c & 7) * 4096;
            bulk_cp(sbW + 8192,  Wh + bofs, 8192, mb);
            bulk_cp(sbW + 16384, Wl + bofs, 8192, mb);
            if (!CONVA) {
                const __nv_bfloat16* Ah = s1 ? a2h : a1h;
                const __nv_bfloat16* Al = s1 ? a2l : a1l;
                const size_t aofs = (size_t)blockIdx.x * 16384 + (size_t)(c & 7) * 2048;
                bulk_cp(sbW,        Ah + aofs, 4096, mb);
                bulk_cp(sbW + 4096, Al + aofs, 4096, mb);
            }
        }
    };

    stage(0);
    for (int c = 0; c < nchunks; ++c) {
        if (c + 1 < nchunks) stage(c + 1);
        mbar_wait((c & 1) ? mb1 : mb0, (uint32_t)((c >> 1) & 1));
        __syncthreads();

        const uint32_t sb = smemB + (uint32_t)(c & 1) * STG_B;

#pragma unroll
        for (int kk = 0; kk < 32; kk += 16) {
            const int gk = kk >> 3;
            uint32_t afh[2][4], afl[2][4];
#pragma unroll
            for (int mi = 0; mi < 2; ++mi) {
                const int row = rA + 16 * mi;
                const uint32_t off =
                    (uint32_t)(row * 64 + (((gk + gA + row + (row >> 2)) & 3) << 4));
                ldsm_x4(afh[mi], sb + off);
                ldsm_x4(afl[mi], sb + 4096 + off);
            }
#pragma unroll
            for (int njp = 0; njp < NJP; ++njp) {
                const int rowb = rB + 16 * njp;
                const uint32_t offb =
                    (uint32_t)(rowb * 64 + (((gk + gB + rowb + (rowb >> 2)) & 3) << 4));
                uint32_t bh[4], bl[4];
                ldsm_x4(bh, sb + 8192 + offb);
                ldsm_x4(bl, sb + 16384 + offb);
#pragma unroll
                for (int mi = 0; mi < 2; ++mi) {
                    mma16816(acc[mi][2 * njp],     afh[mi], bh);
                    mma16816(acc[mi][2 * njp],     afh[mi], bl);
                    mma16816(acc[mi][2 * njp],     afl[mi], bh);
                    mma16816(acc[mi][2 * njp + 1], afh[mi], bh + 2);
                    mma16816(acc[mi][2 * njp + 1], afh[mi], bl + 2);
                    mma16816(acc[mi][2 * njp + 1], afl[mi], bh + 2);
                }
            }
        }
        __syncthreads();
    }

    // ---- epilogue: bias (MODE 0/2) + gelu (all) ----
#pragma unroll
    for (int mi = 0; mi < 2; ++mi)
#pragma unroll
        for (int nj = 0; nj < NJ; ++nj)
#pragma unroll
            for (int q = 0; q < 4; ++q) {
                float v = acc[mi][nj][q];
                if (MODE == 0 || MODE == 2) v += bias[n0 + nw + 8 * nj + tig * 2 + (q & 1)];
                acc[mi][nj][q] = gelu_f(v);
            }

    if (MODE == 3) {          // SAGE pre-LN: gelu -> tmp (fp32, row-major)
#pragma unroll
        for (int mi = 0; mi < 2; ++mi)
#pragma unroll
            for (int half = 0; half < 2; ++half) {
                const int m = m0 + mw + 16 * mi + gid + 8 * half;
                if (m >= M) continue;
#pragma unroll
                for (int nj = 0; nj < NJ; ++nj) {
                    const int ng = n0 + nw + 8 * nj + tig * 2;
                    *reinterpret_cast<float2*>(outF + (size_t)m * HID + ng) =
                        make_float2(acc[mi][nj][2 * half], acc[mi][nj][2 * half + 1]);
                }
            }
    } else if (MODE == 0) {   // ENC: h row-major + blocked splits
#pragma unroll
        for (int mi = 0; mi < 2; ++mi)
#pragma unroll
            for (int half = 0; half < 2; ++half) {
                const int m = m0 + mw + 16 * mi + gid + 8 * half;
                if (m >= M) continue;
#pragma unroll
                for (int nj = 0; nj < NJ; ++nj) {
                    const int ng = n0 + nw + 8 * nj + tig * 2;
                    const float v0 = acc[mi][nj][2 * half];
                    const float v1 = acc[mi][nj][2 * half + 1];
                    *reinterpret_cast<float2*>(outF + (size_t)m * HID + ng) =
                        make_float2(v0, v1);
                    __nv_bfloat162 hv, lv;
                    hv.x = __float2bfloat16(v0); hv.y = __float2bfloat16(v1);
                    lv.x = __float2bfloat16(v0 - __bfloat162float(hv.x));
                    lv.y = __float2bfloat16(v1 - __bfloat162float(hv.y));
                    const int o = boffA(m, ng);
                    *reinterpret_cast<__nv_bfloat162*>(&outH[o]) = hv;
                    *reinterpret_cast<__nv_bfloat162*>(&outL[o]) = lv;
                }
            }
    } else {                  // MODE 2: CLS — dot with w2 + sigmoid (n0 == 0)
#pragma unroll
        for (int mi = 0; mi < 2; ++mi)
#pragma unroll
            for (int half = 0; half < 2; ++half) {
                float d = 0.0f;
#pragma unroll
                for (int nj = 0; nj < NJ; ++nj) {
                    const int ng = nw + 8 * nj + tig * 2;
                    d = fmaf(acc[mi][nj][2 * half], cw2[ng],
                        fmaf(acc[mi][nj][2 * half + 1], cw2[ng + 1], d));
                }
                d += __shfl_xor_sync(0xffffffffu, d, 1);
                d += __shfl_xor_sync(0xffffffffu, d, 2);
                if (tig == 0) {
                    const int rl = mw + 16 * mi + gid + 8 * half;
                    red[rl][wid & 3] = d;
                }
            }
        __syncthreads();
        if ((wid & 3) == 0 && tig == 0) {
#pragma unroll
            for (int mi = 0; mi < 2; ++mi)
#pragma unroll
                for (int half = 0; half < 2; ++half) {
                    const int rl = mw + 16 * mi + gid + 8 * half;
                    const int m = m0 + rl;
                    if (m >= M) continue;
                    const float logit = red[rl][0] + red[rl][1] +
                                        red[rl][2] + red[rl][3] + cb2[0];
                    outS[m] = 1.0f / (1.0f + expf(-logit));
                }
        }
    }
}

// ================= layernorm + residual (reads tmp; emits h + blocked splits) =
__global__ void ln_res_kernel(const float* __restrict__ x, const float* __restrict__ g,
                              const float* __restrict__ b, float* __restrict__ h,
                              __nv_bfloat16* __restrict__ ah, __nv_bfloat16* __restrict__ al,
                              int writeH) {
    const int n = blockIdx.x;
    const int d = threadIdx.x;
    __shared__ float red[8];
    __shared__ float s_mu, s_rstd;

    const float v = x[(size_t)n * HID + d];
    float s = v;
#pragma unroll
    for (int o = 16; o > 0; o >>= 1) s += __shfl_xor_sync(0xffffffffu, s, o);
    if ((d & 31) == 0) red[d >> 5] = s;
    __syncthreads();
    if (d == 0) {
        float t = 0.0f;
        for (int i = 0; i < 8; ++i) t += red[i];
        s_mu = t * (1.0f / HID);
    }
    __syncthreads();
    const float mu = s_mu;
    const float df = v - mu;
    float q = df * df;
#pragma unroll
    for (int o = 16; o > 0; o >>= 1) q += __shfl_xor_sync(0xffffffffu, q, o);
    __syncthreads();
    if ((d & 31) == 0) red[d >> 5] = q;
    __syncthreads();
    if (d == 0) {
        float t = 0.0f;
        for (int i = 0; i < 8; ++i) t += red[i];
        s_rstd = rsqrtf(t * (1.0f / HID) + 1e-5f);
    }
    __syncthreads();
    const float hv = h[(size_t)n * HID + d] + df * s_rstd * g[d] + b[d];
    if (writeH) h[(size_t)n * HID + d] = hv;
    const __nv_bfloat16 hi = __float2bfloat16(hv);
    const int o = boffA(n, d);
    ah[o] = hi;
    al[o] = __float2bfloat16(hv - __bfloat162float(hi));
}

// ================= neighbor aggregation (emits blocked bf16 split) ============
__global__ void agg_kernel(const float* __restrict__ h, const int* __restrict__ nidx,
                           const float* __restrict__ nw,
                           __nv_bfloat16* __restrict__ gh, __nv_bfloat16* __restrict__ gl) {
    const int n = blockIdx.x;
    const int d = threadIdx.x;
    __shared__ int   sidx[KNB];
    __shared__ float sw  [KNB];
    if (d < KNB) { sidx[d] = nidx[n * KNB + d]; sw[d] = nw[n * KNB + d]; }
    __syncthreads();
    float acc = 0.0f;
#pragma unroll
    for (int k = 0; k < KNB; ++k)
        acc = fmaf(sw[k], h[(size_t)sidx[k] * HID + d], acc);
    const __nv_bfloat16 hi = __float2bfloat16(acc);
    const int o = boffA(n, d);
    gh[o] = hi;
    gl[o] = __float2bfloat16(acc - __bfloat162float(hi));
}

// ================= launch =======================================================
extern "C" void kernel_launch(void* const* d_in, const int* in_sizes, int n_in,
                              void* d_out, int out_size) {
    const float* feats  = (const float*)d_in[0];
    const float* cents  = (const float*)d_in[1];
    const float* enc_w  = (const float*)d_in[2];
    const float* enc_b  = (const float*)d_in[3];
    const float* g1_ws  = (const float*)d_in[4];
    const float* g1_wn  = (const float*)d_in[5];
    const float* g1_g   = (const float*)d_in[6];
    const float* g1_b   = (const float*)d_in[7];
    const float* g2_ws  = (const float*)d_in[8];
    const float* g2_wn  = (const float*)d_in[9];
    const float* g2_g   = (const float*)d_in[10];
    const float* g2_b   = (const float*)d_in[11];
    const float* cls_w1 = (const float*)d_in[12];
    const float* cls_b1 = (const float*)d_in[13];
    const float* cls_w2 = (const float*)d_in[14];
    const float* cls_b2 = (const float*)d_in[15];
    float* out = (float*)d_out;

    float *p_h, *p_tmp, *p_nw;
    int* p_nidx;
    __nv_bfloat16 *p_ah, *p_al, *p_gh, *p_gl, *p_wh, *p_wl;
    cudaGetSymbolAddress((void**)&p_h,    g_h);
    cudaGetSymbolAddress((void**)&p_tmp,  g_tmp);
    cudaGetSymbolAddress((void**)&p_nidx, g_nidx);
    cudaGetSymbolAddress((void**)&p_nw,   g_nw);
    cudaGetSymbolAddress((void**)&p_ah,   g_ah);
    cudaGetSymbolAddress((void**)&p_al,   g_al);
    cudaGetSymbolAddress((void**)&p_gh,   g_gh);
    cudaGetSymbolAddress((void**)&p_gl,   g_gl);
    cudaGetSymbolAddress((void**)&p_wh,   g_wh);
    cudaGetSymbolAddress((void**)&p_wl,   g_wl);

    const int M = NPTS;
    const int NBLK = (M + 63) / 64;   // 188
    const int SMEM = 2 * STG_B;       // 49152

    cudaFuncSetAttribute(hmma_gemm_kernel<0, false, true >,
                         cudaFuncAttributeMaxDynamicSharedMemorySize, SMEM);
    cudaFuncSetAttribute(hmma_gemm_kernel<3, true,  false>,
                         cudaFuncAttributeMaxDynamicSharedMemorySize, SMEM);
    cudaFuncSetAttribute(hmma_gemm_kernel<2, false, false>,
                         cudaFuncAttributeMaxDynamicSharedMemorySize, SMEM);

    cudaStream_t s2;
    cudaStreamCreateWithFlags(&s2, cudaStreamNonBlocking);
    cudaEvent_t evF, evJ;
    cudaEventCreateWithFlags(&evF, cudaEventDisableTiming);
    cudaEventCreateWithFlags(&evJ, cudaEventDisableTiming);
    cudaEventRecord(evF, 0);
    cudaStreamWaitEvent(s2, evF, 0);

    const dim3 gFull(NBLK, 2);
    const dim3 gCls(NBLK, 1);

    // ---- s2: KNN (fused build + fast query) ----
    knn_build_kernel<<<1, 1024, 0, s2>>>(cents);
    knn_query_kernel<<<(NPTS * 32 + 255) / 256, 256, 0, s2>>>(p_nidx, p_nw);
    cudaEventRecord(evJ, s2);

    // ---- main: encoder-slice split -> encoder -> remaining splits in slack ----
    split_w_kernel<<<(WENC + 255) / 256, 256>>>(
        enc_w, g1_ws, g1_wn, g2_ws, g2_wn, cls_w1, 0, WENC);
    hmma_gemm_kernel<0, false, true><<<gFull, 256, SMEM>>>(
        nullptr, nullptr, feats, p_wh + 0, p_wl + 0,
        nullptr, nullptr, nullptr, nullptr,
        enc_b, nullptr, nullptr, nullptr,
        p_h, p_ah, p_al, M);
    split_w_kernel<<<(WTOT - WENC + 255) / 256, 256>>>(
        enc_w, g1_ws, g1_wn, g2_ws, g2_wn, cls_w1, WENC, WTOT);

    // join: agg needs knn graph + h
    cudaStreamWaitEvent(0, evJ, 0);

    // ---- SAGE layer 1 ----
    agg_kernel<<<NPTS, HID>>>(p_h, p_nidx, p_nw, p_gh, p_gl);
    hmma_gemm_kernel<3, true, false><<<gFull, 256, SMEM>>>(
        p_ah, p_al, nullptr, p_wh + 65536, p_wl + 65536,
        p_gh, p_gl, p_wh + 131072, p_wl + 131072,
        nullptr, nullptr, nullptr, nullptr,
        p_tmp, nullptr, nullptr, M);
    ln_res_kernel<<<NPTS, HID>>>(p_tmp, g1_g, g1_b, p_h, p_ah, p_al, 1);

    // ---- SAGE layer 2 ----
    agg_kernel<<<NPTS, HID>>>(p_h, p_nidx, p_nw, p_gh, p_gl);
    hmma_gemm_kernel<3, true, false><<<gFull, 256, SMEM>>>(
        p_ah, p_al, nullptr, p_wh + 196608, p_wl + 196608,
        p_gh, p_gl, p_wh + 262144, p_wl + 262144,
        nullptr, nullptr, nullptr, nullptr,
        p_tmp, nullptr, nullptr, M);
    ln_res_kernel<<<NPTS, HID>>>(p_tmp, g2_g, g2_b, p_h, p_ah, p_al, 0);

    // ---- classifier (fused dot + sigmoid) ----
    hmma_gemm_kernel<2, false, false><<<gCls, 256, SMEM>>>(
        p_ah, p_al, nullptr, p_wh + 327680, p_wl + 327680,
        nullptr, nullptr, nullptr, nullptr,
        cls_b1, cls_w2, cls_b2, out,
        nullptr, nullptr, nullptr, M);
}

// round 17
// speedup vs baseline: 1.6068x; 1.0018x over previous
#include <cuda_runtime.h>
#include <cuda_bf16.h>
#include <cstdint>
#include <cfloat>
#include <math.h>

#define NPTS 12000
#define MPAD 12032
#define HID  256
#define KNB  16
#define G    64
#define NCELL (G * G)

// ---------------- scratch (allocation-free: __device__ globals) --------------
__device__ float g_h   [MPAD * HID];
__device__ float g_tmp [MPAD * HID];
__device__ float g_tmp2[MPAD * HID];
__device__ int   g_nidx[NPTS * KNB];
__device__ float g_nw  [NPTS * KNB];

// blocked bf16 split operand buffers (tile/chunk blocked, swizzled)
__device__ __nv_bfloat16 g_ah[MPAD * HID], g_al[MPAD * HID];   // h split
__device__ __nv_bfloat16 g_gh[MPAD * HID], g_gl[MPAD * HID];   // agg split
#define WTOT 360448
#define WENC 65536
__device__ __nv_bfloat16 g_wh[WTOT], g_wl[WTOT];
// slots: enc=0, g1ws=65536, g1wn=131072, g2ws=196608, g2wn=262144, cls=327680

// grid-knn scratch
__device__ unsigned int g_bbox[4];
__device__ int    g_cellstart[NCELL + 1];
__device__ float2 g_pts [NPTS];
__device__ int    g_sidx[NPTS];

__device__ __forceinline__ float gelu_f(float x) {
    return 0.5f * x * (1.0f + erff(x * 0.70710678118654752440f));
}

__device__ __forceinline__ unsigned int fenc(float f) {
    unsigned int u = __float_as_uint(f);
    return (u & 0x80000000u) ? ~u : (u | 0x80000000u);
}
__device__ __forceinline__ float fdec(unsigned int u) {
    return __uint_as_float((u & 0x80000000u) ? (u ^ 0x80000000u) : ~u);
}

__device__ __forceinline__ uint32_t smem_u32(const void* p) {
    uint32_t a;
    asm("{ .reg .u64 t; cvta.to.shared.u64 t, %1; cvt.u32.u64 %0, t; }" : "=r"(a) : "l"(p));
    return a;
}
__device__ __forceinline__ void ldsm_x4(uint32_t* r, uint32_t addr) {
    asm volatile("ldmatrix.sync.aligned.m8n8.x4.shared.b16 {%0,%1,%2,%3}, [%4];"
                 : "=r"(r[0]), "=r"(r[1]), "=r"(r[2]), "=r"(r[3]) : "r"(addr));
}
__device__ __forceinline__ void bulk_cp(uint32_t dst, const void* src, uint32_t bytes,
                                        uint32_t mbar) {
    asm volatile(
        "cp.async.bulk.shared::cta.global.mbarrier::complete_tx::bytes [%0], [%1], %2, [%3];"
        :: "r"(dst), "l"(src), "r"(bytes), "r"(mbar) : "memory");
}
#define MBAR_INIT(mb, c) \
    asm volatile("mbarrier.init.shared.b64 [%0], %1;" :: "r"((uint32_t)(mb)), "r"((uint32_t)(c)) : "memory")
#define MBAR_EXPECT(mb, tx) \
    asm volatile("mbarrier.arrive.expect_tx.shared.b64 _, [%0], %1;" \
                 :: "r"((uint32_t)(mb)), "r"((uint32_t)(tx)) : "memory")
__device__ __forceinline__ void mbar_wait(uint32_t mb, uint32_t parity) {
    asm volatile(
        "{\n\t.reg .pred P;\n\t"
        "W_%=:\n\t"
        "mbarrier.try_wait.parity.acquire.cta.shared::cta.b64 P, [%0], %1, 0x989680;\n\t"
        "@!P bra.uni W_%=;\n\t"
        "}" :: "r"(mb), "r"(parity) : "memory");
}

// HMMA: D(f32) += A(bf16,row) * B(bf16,col), m16n8k16
__device__ __forceinline__ void mma16816(float* c, const uint32_t* a, const uint32_t* b) {
    asm volatile(
        "mma.sync.aligned.m16n8k16.row.col.f32.bf16.bf16.f32 "
        "{%0,%1,%2,%3}, {%4,%5,%6,%7}, {%8,%9}, {%0,%1,%2,%3};"
        : "+f"(c[0]), "+f"(c[1]), "+f"(c[2]), "+f"(c[3])
        : "r"(a[0]), "r"(a[1]), "r"(a[2]), "r"(a[3]), "r"(b[0]), "r"(b[1]));
}

// blocked+swizzled layouts.
__device__ __forceinline__ int boffA(int m, int d) {
    return ((m >> 6) << 14) | ((d >> 5) << 11) | ((m & 63) << 5) |
           ((((d >> 3) + m + (m >> 2)) & 3) << 3) | (d & 7);
}
__device__ __forceinline__ int boffB(int n, int k) {
    return ((n >> 7) << 15) | ((k >> 5) << 12) | ((n & 127) << 5) |
           ((((k >> 3) + n + (n >> 2)) & 3) << 3) | (k & 7);
}

// ================= KNN build: ONE CTA does bbox+count+scan+scatter =============
__global__ __launch_bounds__(1024) void knn_build_kernel(const float* __restrict__ cents) {
    __shared__ int   scnt[NCELL];
    __shared__ float rmnx[32], rmxx[32], rmny[32], rmxy[32];
    __shared__ float sbb[4];
    __shared__ int   wsum[32];
    const int t = threadIdx.x;
    const int lane = t & 31;
    const int warp = t >> 5;

    float2 pts[12];
    int np = 0;
    for (int i = t; i < NPTS; i += 1024) pts[np++] = *reinterpret_cast<const float2*>(cents + 2 * i);

    float xmn = FLT_MAX, xmx = -FLT_MAX, ymn = FLT_MAX, ymx = -FLT_MAX;
    for (int j = 0; j < np; ++j) {
        xmn = fminf(xmn, pts[j].x); xmx = fmaxf(xmx, pts[j].x);
        ymn = fminf(ymn, pts[j].y); ymx = fmaxf(ymx, pts[j].y);
    }
#pragma unroll
    for (int o = 16; o > 0; o >>= 1) {
        xmn = fminf(xmn, __shfl_xor_sync(0xffffffffu, xmn, o));
        xmx = fmaxf(xmx, __shfl_xor_sync(0xffffffffu, xmx, o));
        ymn = fminf(ymn, __shfl_xor_sync(0xffffffffu, ymn, o));
        ymx = fmaxf(ymx, __shfl_xor_sync(0xffffffffu, ymx, o));
    }
    if (lane == 0) { rmnx[warp] = xmn; rmxx[warp] = xmx; rmny[warp] = ymn; rmxy[warp] = ymx; }
    __syncthreads();
    if (t == 0) {
        float a = rmnx[0], b = rmxx[0], c = rmny[0], d = rmxy[0];
        for (int i = 1; i < 32; ++i) {
            a = fminf(a, rmnx[i]); b = fmaxf(b, rmxx[i]);
            c = fminf(c, rmny[i]); d = fmaxf(d, rmxy[i]);
        }
        sbb[0] = a; sbb[1] = b; sbb[2] = c; sbb[3] = d;
        g_bbox[0] = fenc(a); g_bbox[1] = fenc(b);
        g_bbox[2] = fenc(c); g_bbox[3] = fenc(d);
    }
    for (int c = t; c < NCELL; c += 1024) scnt[c] = 0;
    __syncthreads();

    const float xmin = sbb[0], ymin = sbb[2];
    const float rx = fmaxf(sbb[1] - xmin, 1e-20f);
    const float ry = fmaxf(sbb[3] - ymin, 1e-20f);
    const float iwx = (float)G / rx, iwy = (float)G / ry;

    int cellid[12];
    for (int j = 0; j < np; ++j) {
        int cx = (int)((pts[j].x - xmin) * iwx); cx = min(max(cx, 0), G - 1);
        int cy = (int)((pts[j].y - ymin) * iwy); cy = min(max(cy, 0), G - 1);
        cellid[j] = cy * G + cx;
        atomicAdd(&scnt[cellid[j]], 1);
    }
    __syncthreads();

    const int base = t * 4;
    int loc[4];
    int s = 0;
#pragma unroll
    for (int j = 0; j < 4; ++j) { loc[j] = s; s += scnt[base + j]; }
    int v = s;
#pragma unroll
    for (int o = 1; o < 32; o <<= 1) {
        const int n = __shfl_up_sync(0xffffffffu, v, o);
        if (lane >= o) v += n;
    }
    if (lane == 31) wsum[warp] = v;
    __syncthreads();
    if (t == 0) {
        int run = 0;
        for (int i = 0; i < 32; ++i) { const int tmp = wsum[i]; wsum[i] = run; run += tmp; }
    }
    __syncthreads();
    const int pre = wsum[warp] + (v - s);
#pragma unroll
    for (int j = 0; j < 4; ++j) loc[j] += pre;
#pragma unroll
    for (int j = 0; j < 4; ++j) g_cellstart[base + j] = loc[j];
    if (t == 1023) g_cellstart[NCELL] = NPTS;
    __syncthreads();
#pragma unroll
    for (int j = 0; j < 4; ++j) scnt[base + j] = loc[j];
    __syncthreads();

    for (int j = 0; j < np; ++j) {
        const int slot = atomicAdd(&scnt[cellid[j]], 1);
        g_pts [slot] = pts[j];
        g_sidx[slot] = t + 1024 * j;
    }
}

__device__ __forceinline__ void grid_params(float& xmin, float& ymin,
                                            float& iwx, float& iwy,
                                            float& wx, float& wy) {
    xmin = fdec(g_bbox[0]);
    const float xmax = fdec(g_bbox[1]);
    ymin = fdec(g_bbox[2]);
    const float ymax = fdec(g_bbox[3]);
    const float rx = fmaxf(xmax - xmin, 1e-20f);
    const float ry = fmaxf(ymax - ymin, 1e-20f);
    iwx = (float)G / rx; iwy = (float)G / ry;
    wx = rx / (float)G;  wy = ry / (float)G;
}

__device__ __forceinline__ int cell_x(float x, float xmin, float iwx) {
    int c = (int)((x - xmin) * iwx);
    return min(max(c, 0), G - 1);
}

// ================= KNN query: warp/query, LANE-DISTRIBUTED shared top-16 ======
__global__ void knn_query_kernel(int* __restrict__ nidx, float* __restrict__ nw) {
    const int w = (blockIdx.x * blockDim.x + threadIdx.x) >> 5;
    const int lane = threadIdx.x & 31;
    if (w >= NPTS) return;
    const int s = w;
    const float2 q = g_pts[s];
    const int i = g_sidx[s];

    float xmin, ymin, iwx, iwy, wx, wy;
    grid_params(xmin, ymin, iwx, iwy, wx, wy);
    const int cx = cell_x(q.x, xmin, iwx);
    const int cy = cell_x(q.y, ymin, iwy);

    float slotval = (lane < KNB) ? FLT_MAX : -FLT_MAX;
    int   slotid  = 0;
    float maxv = FLT_MAX;

    for (int r = 0; r < G; ++r) {
        const int ylo = max(cy - r, 0), yhi = min(cy + r, G - 1);
        for (int vy = ylo; vy <= yhi; ++vy) {
            const bool edge_row = (vy == cy - r) || (vy == cy + r);
            int ps0 = 0, pe0 = 0, ps1 = 0, pe1 = 0;
            if (edge_row) {
                const int xl = max(cx - r, 0), xh = min(cx + r, G - 1);
                ps0 = g_cellstart[vy * G + xl];
                pe0 = g_cellstart[vy * G + xh + 1];
            } else {
                if (cx - r >= 0) {
                    ps0 = g_cellstart[vy * G + cx - r];
                    pe0 = g_cellstart[vy * G + cx - r + 1];
                }
                if (cx + r <= G - 1) {
                    ps1 = g_cellstart[vy * G + cx + r];
                    pe1 = g_cellstart[vy * G + cx + r + 1];
                }
            }
#pragma unroll
            for (int seg = 0; seg < 2; ++seg) {
                const int ps = seg ? ps1 : ps0;
                const int pe = seg ? pe1 : pe0;
                for (int p0 = ps; p0 < pe; p0 += 32) {
                    const int p = p0 + lane;
                    float d2 = FLT_MAX;
                    if (p < pe && p != s) {
                        const float2 f = g_pts[p];
                        const float dx = q.x - f.x;
                        const float dy = q.y - f.y;
                        d2 = fmaf(dx, dx, dy * dy);
                    }
                    unsigned int m = __ballot_sync(0xffffffffu, d2 < maxv);
                    while (m) {
                        const int l = __ffs(m) - 1;
                        m &= m - 1;
                        const float dd = __shfl_sync(0xffffffffu, d2, l);
                        if (dd < maxv) {
                            const int pp = __shfl_sync(0xffffffffu, p, l);
                            const unsigned int own =
                                __ballot_sync(0xffffffffu, slotval == maxv);
                            const int ol = __ffs(own) - 1;
                            if (lane == ol) { slotval = dd; slotid = pp; }
                            float mx = slotval;
#pragma unroll
                            for (int o = 16; o > 0; o >>= 1)
                                mx = fmaxf(mx, __shfl_xor_sync(0xffffffffu, mx, o));
                            maxv = mx;
                        }
                    }
                }
            }
        }
        if (maxv < FLT_MAX) {
            const float bl = (cx - r > 0)     ? q.x - (xmin + (float)(cx - r) * wx)     : FLT_MAX;
            const float br = (cx + r < G - 1) ? (xmin + (float)(cx + r + 1) * wx) - q.x : FLT_MAX;
            const float bb = (cy - r > 0)     ? q.y - (ymin + (float)(cy - r) * wy)     : FLT_MAX;
            const float bt = (cy + r < G - 1) ? (ymin + (float)(cy + r + 1) * wy) - q.y : FLT_MAX;
            const float b = fminf(fminf(bl, br), fminf(bb, bt));
            if (b == FLT_MAX || (b > 0.0f && b * b > maxv)) break;
        }
    }

    float invd = 0.0f;
    int oid = 0;
    if (lane < KNB) {
        const float2 f = g_pts[slotid];
        oid = g_sidx[slotid];
        const float xi = q.x, yi = q.y;
        const float sqi = __fadd_rn(__fmul_rn(xi, xi), __fmul_rn(yi, yi));
        const float sqj = __fadd_rn(__fmul_rn(f.x, f.x), __fmul_rn(f.y, f.y));
        const float dot = __fadd_rn(__fmul_rn(xi, f.x), __fmul_rn(yi, f.y));
        const float d2  = __fsub_rn(__fadd_rn(sqi, sqj), __fmul_rn(2.0f, dot));
        const float dist = sqrtf(fmaxf(d2, 0.0f));
        invd = 1.0f / fmaxf(dist, 1e-4f);
    }
    float tot = invd;
#pragma unroll
    for (int o = 16; o > 0; o >>= 1)
        tot += __shfl_xor_sync(0xffffffffu, tot, o);
    if (lane < KNB) {
        nidx[i * KNB + lane] = oid;
        nw  [i * KNB + lane] = invd / fmaxf(tot, 1e-8f);
    }
}

// ================= weight split (ranged, writes BLOCKED layout) ================
__global__ void split_w_kernel(const float* __restrict__ w0, const float* __restrict__ w1,
                               const float* __restrict__ w2, const float* __restrict__ w3,
                               const float* __restrict__ w4, const float* __restrict__ w5,
                               int lo, int hi) {
    const int i = lo + blockIdx.x * blockDim.x + threadIdx.x;
    if (i >= hi) return;
    float x;
    int base, r;
    if      (i < 65536)  { x = w0[i];          base = 0;      r = i; }
    else if (i < 131072) { x = w1[i - 65536];  base = 65536;  r = i - 65536; }
    else if (i < 196608) { x = w2[i - 131072]; base = 131072; r = i - 131072; }
    else if (i < 262144) { x = w3[i - 196608]; base = 196608; r = i - 196608; }
    else if (i < 327680) { x = w4[i - 262144]; base = 262144; r = i - 262144; }
    else                 { x = w5[i - 327680]; base = 327680; r = i - 327680; }
    const int n = r >> 8, k = r & 255;
    const int o = base + boffB(n, k);
    const __nv_bfloat16 h = __float2bfloat16(x);
    g_wh[o] = h;
    g_wl[o] = __float2bfloat16(x - __bfloat162float(h));
}

// ================= HMMA GEMM: 3-stage bulk pipeline, 64x128 tiles =============
// 3-term bf16 split. MODE: 0=ENC (bias+gelu -> h + blocked splits),
// 2=CLS (bias+gelu+dot+sigmoid), 3=gelu -> outF fp32 (pre-LN),
// 4=RAW partial -> outF fp32 (no activation). INITC: acc init from cinit.
#define NCOLS 128
#define STG_B 24576   // bytes/stage: Ah 4096 | Al 4096 | Bh 8192 | Bl 8192
template <int MODE, bool DUAL, bool CONVA, bool INITC>
__global__ __launch_bounds__(256, 3) void hmma_gemm_kernel(
    const __nv_bfloat16* __restrict__ a1h, const __nv_bfloat16* __restrict__ a1l,
    const float* __restrict__ a1f,
    const __nv_bfloat16* __restrict__ w1h, const __nv_bfloat16* __restrict__ w1l,
    const __nv_bfloat16* __restrict__ a2h, const __nv_bfloat16* __restrict__ a2l,
    const __nv_bfloat16* __restrict__ w2h, const __nv_bfloat16* __restrict__ w2l,
    const float* __restrict__ bias,
    const float* __restrict__ cw2, const float* __restrict__ cb2,
    float* __restrict__ outS,
    const float* __restrict__ cinit,
    float* outF,
    __nv_bfloat16* __restrict__ outH, __nv_bfloat16* __restrict__ outL, int M) {
    extern __shared__ __nv_bfloat16 smem[];
    __shared__ float red[64][4];
    __shared__ __align__(16) unsigned long long mbars[3];

    constexpr int NJ = NCOLS / 32;     // 4
    constexpr int NJP = NJ / 2;        // 2

    const int tid  = threadIdx.x;
    const int wid  = tid >> 5;
    const int lane = tid & 31;
    const int gid  = lane >> 2;
    const int tig  = lane & 3;
    const int m0 = blockIdx.x * 64;
    const int n0 = blockIdx.y * NCOLS;
    const int mw = (wid >> 2) * 32;
    const int nw = (wid & 3) * 32;
    const int nchunks = DUAL ? 16 : 8;

    const uint32_t smemB = smem_u32(smem);
    uint32_t mbs[3];
    mbs[0] = smem_u32(&mbars[0]);
    mbs[1] = smem_u32(&mbars[1]);
    mbs[2] = smem_u32(&mbars[2]);
    if (tid == 0) { MBAR_INIT(mbs[0], 1); MBAR_INIT(mbs[1], 1); MBAR_INIT(mbs[2], 1); }
    __syncthreads();

    const int rA = mw + (lane & 15);
    const int gA = (lane >> 4) & 1;
    const int rB = nw + 8 * ((lane >> 4) & 1) + (lane & 7);
    const int gB = (lane >> 3) & 1;

    float acc[2][NJ][4];
    if (INITC) {
#pragma unroll
        for (int mi = 0; mi < 2; ++mi)
#pragma unroll
            for (int half = 0; half < 2; ++half) {
                const int m = m0 + mw + 16 * mi + gid + 8 * half;
#pragma unroll
                for (int nj = 0; nj < NJ; ++nj) {
                    const int ng = n0 + nw + 8 * nj + tig * 2;
                    float2 t = make_float2(0.f, 0.f);
                    if (m < M)
                        t = *reinterpret_cast<const float2*>(cinit + (size_t)m * HID + ng);
                    acc[mi][nj][2 * half] = t.x;
                    acc[mi][nj][2 * half + 1] = t.y;
                }
            }
    } else {
#pragma unroll
        for (int a = 0; a < 2; ++a)
#pragma unroll
            for (int b = 0; b < NJ; ++b)
#pragma unroll
                for (int c = 0; c < 4; ++c) acc[a][b][c] = 0.0f;
    }

    auto stage = [&](int c) {
        const int buf = c % 3;
        const uint32_t sbW = smemB + (uint32_t)buf * STG_B;
        if (CONVA) {
            const int r = tid >> 2, qd = tid & 3;
            const uint32_t off = (uint32_t)(r * 64 + (((qd + r + (r >> 2)) & 3) << 4));
            const int mg = m0 + r;
            __align__(16) __nv_bfloat16 hh[8], ll[8];
            if (mg < M) {
                const float* fp = a1f + (size_t)mg * HID + (c & 7) * 32 + qd * 8;
                const float4 f0 = *reinterpret_cast<const float4*>(fp);
                const float4 f1 = *reinterpret_cast<const float4*>(fp + 4);
                const float fv[8] = {f0.x, f0.y, f0.z, f0.w, f1.x, f1.y, f1.z, f1.w};
#pragma unroll
                for (int j = 0; j < 8; ++j) {
                    hh[j] = __float2bfloat16(fv[j]);
                    ll[j] = __float2bfloat16(fv[j] - __bfloat162float(hh[j]));
                }
            } else {
#pragma unroll
                for (int j = 0; j < 8; ++j) { hh[j] = __nv_bfloat16(0.f); ll[j] = __nv_bfloat16(0.f); }
            }
            *reinterpret_cast<uint4*>(smem + (uint32_t)buf * (STG_B >> 1) + (off >> 1)) =
                *reinterpret_cast<const uint4*>(hh);
            *reinterpret_cast<uint4*>(smem + (uint32_t)buf * (STG_B >> 1) + ((off + 4096) >> 1)) =
                *reinterpret_cast<const uint4*>(ll);
        }
        if (tid == 0) {
            const uint32_t mb = mbs[buf];
            MBAR_EXPECT(mb, CONVA ? 16384u : 24576u);
            const bool s1 = DUAL && (c >= 8);
            const __nv_bfloat16* Wh = s1 ? w2h : w1h;
            const __nv_bfloat16* Wl = s1 ? w2l : w1l;
            const size_t bofs = (size_t)blockIdx.y * 32768 + (size_t)(c & 7) * 4096;
            bulk_cp(sbW + 8192,  Wh + bofs, 8192, mb);
            bulk_cp(sbW + 16384, Wl + bofs, 8192, mb);
            if (!CONVA) {
                const __nv_bfloat16* Ah = s1 ? a2h : a1h;
                const __nv_bfloat16* Al = s1 ? a2l : a1l;
                const size_t aofs = (size_t)blockIdx.x * 16384 + (size_t)(c & 7) * 2048;
                bulk_cp(sbW,        Ah + aofs, 4096, mb);
                bulk_cp(sbW + 4096, Al + aofs, 4096, mb);
            }
        }
    };

    stage(0);
    if (nchunks > 1) stage(1);
    for (int c = 0; c < nchunks; ++c) {
        mbar_wait(mbs[c % 3], (uint32_t)((c / 3) & 1));
        __syncthreads();

        const uint32_t sb = smemB + (uint32_t)(c % 3) * STG_B;

#pragma unroll
        for (int kk = 0; kk < 32; kk += 16) {
            const int gk = kk >> 3;
            uint32_t afh[2][4], afl[2][4];
#pragma unroll
            for (int mi = 0; mi < 2; ++mi) {
                const int row = rA + 16 * mi;
                const uint32_t off =
                    (uint32_t)(row * 64 + (((gk + gA + row + (row >> 2)) & 3) << 4));
                ldsm_x4(afh[mi], sb + off);
                ldsm_x4(afl[mi], sb + 4096 + off);
            }
#pragma unroll
            for (int njp = 0; njp < NJP; ++njp) {
                const int rowb = rB + 16 * njp;
                const uint32_t offb =
                    (uint32_t)(rowb * 64 + (((gk + gB + rowb + (rowb >> 2)) & 3) << 4));
                uint32_t bh[4], bl[4];
                ldsm_x4(bh, sb + 8192 + offb);
                ldsm_x4(bl, sb + 16384 + offb);
#pragma unroll
                for (int mi = 0; mi < 2; ++mi) {
                    mma16816(acc[mi][2 * njp],     afh[mi], bh);
                    mma16816(acc[mi][2 * njp],     afh[mi], bl);
                    mma16816(acc[mi][2 * njp],     afl[mi], bh);
                    mma16816(acc[mi][2 * njp + 1], afh[mi], bh + 2);
                    mma16816(acc[mi][2 * njp + 1], afh[mi], bl + 2);
                    mma16816(acc[mi][2 * njp + 1], afl[mi], bh + 2);
                }
            }
        }
        __syncthreads();
        if (c + 2 < nchunks) stage(c + 2);
    }

    // ---- epilogue ----
    if (MODE != 4) {
#pragma unroll
        for (int mi = 0; mi < 2; ++mi)
#pragma unroll
            for (int nj = 0; nj < NJ; ++nj)
#pragma unroll
                for (int q = 0; q < 4; ++q) {
                    float v = acc[mi][nj][q];
                    if (MODE == 0 || MODE == 2)
                        v += bias[n0 + nw + 8 * nj + tig * 2 + (q & 1)];
                    acc[mi][nj][q] = gelu_f(v);
                }
    }

    if (MODE == 3 || MODE == 4) {   // fp32 partial / pre-LN out
#pragma unroll
        for (int mi = 0; mi < 2; ++mi)
#pragma unroll
            for (int half = 0; half < 2; ++half) {
                const int m = m0 + mw + 16 * mi + gid + 8 * half;
                if (m >= M) continue;
#pragma unroll
                for (int nj = 0; nj < NJ; ++nj) {
                    const int ng = n0 + nw + 8 * nj + tig * 2;
                    *reinterpret_cast<float2*>(outF + (size_t)m * HID + ng) =
                        make_float2(acc[mi][nj][2 * half], acc[mi][nj][2 * half + 1]);
                }
            }
    } else if (MODE == 0) {   // ENC: h row-major + blocked splits
#pragma unroll
        for (int mi = 0; mi < 2; ++mi)
#pragma unroll
            for (int half = 0; half < 2; ++half) {
                const int m = m0 + mw + 16 * mi + gid + 8 * half;
                if (m >= M) continue;
#pragma unroll
                for (int nj = 0; nj < NJ; ++nj) {
                    const int ng = n0 + nw + 8 * nj + tig * 2;
                    const float v0 = acc[mi][nj][2 * half];
                    const float v1 = acc[mi][nj][2 * half + 1];
                    *reinterpret_cast<float2*>(outF + (size_t)m * HID + ng) =
                        make_float2(v0, v1);
                    __nv_bfloat162 hv, lv;
                    hv.x = __float2bfloat16(v0); hv.y = __float2bfloat16(v1);
                    lv.x = __float2bfloat16(v0 - __bfloat162float(hv.x));
                    lv.y = __float2bfloat16(v1 - __bfloat162float(hv.y));
                    const int o = boffA(m, ng);
                    *reinterpret_cast<__nv_bfloat162*>(&outH[o]) = hv;
                    *reinterpret_cast<__nv_bfloat162*>(&outL[o]) = lv;
                }
            }
    } else {                  // MODE 2: CLS — dot with w2 + sigmoid (n0 == 0)
#pragma unroll
        for (int mi = 0; mi < 2; ++mi)
#pragma unroll
            for (int half = 0; half < 2; ++half) {
                float d = 0.0f;
#pragma unroll
                for (int nj = 0; nj < NJ; ++nj) {
                    const int ng = nw + 8 * nj + tig * 2;
                    d = fmaf(acc[mi][nj][2 * half], cw2[ng],
                        fmaf(acc[mi][nj][2 * half + 1], cw2[ng + 1], d));
                }
                d += __shfl_xor_sync(0xffffffffu, d, 1);
                d += __shfl_xor_sync(0xffffffffu, d, 2);
                if (tig == 0) {
                    const int rl = mw + 16 * mi + gid + 8 * half;
                    red[rl][wid & 3] = d;
                }
            }
        __syncthreads();
        if ((wid & 3) == 0 && tig == 0) {
#pragma unroll
            for (int mi = 0; mi < 2; ++mi)
#pragma unroll
                for (int half = 0; half < 2; ++half) {
                    const int rl = mw + 16 * mi + gid + 8 * half;
                    const int m = m0 + rl;
                    if (m >= M) continue;
                    const float logit = red[rl][0] + red[rl][1] +
                                        red[rl][2] + red[rl][3] + cb2[0];
                    outS[m] = 1.0f / (1.0f + expf(-logit));
                }
        }
    }
}

// ================= layernorm + residual (reads tmp; emits h + blocked splits) =
__global__ void ln_res_kernel(const float* __restrict__ x, const float* __restrict__ g,
                              const float* __restrict__ b, float* __restrict__ h,
                              __nv_bfloat16* __restrict__ ah, __nv_bfloat16* __restrict__ al,
                              int writeH) {
    const int n = blockIdx.x;
    const int d = threadIdx.x;
    __shared__ float red[8];
    __shared__ float s_mu, s_rstd;

    const float v = x[(size_t)n * HID + d];
    float s = v;
#pragma unroll
    for (int o = 16; o > 0; o >>= 1) s += __shfl_xor_sync(0xffffffffu, s, o);
    if ((d & 31) == 0) red[d >> 5] = s;
    __syncthreads();
    if (d == 0) {
        float t = 0.0f;
        for (int i = 0; i < 8; ++i) t += red[i];
        s_mu = t * (1.0f / HID);
    }
    __syncthreads();
    const float mu = s_mu;
    const float df = v - mu;
    float q = df * df;
#pragma unroll
    for (int o = 16; o > 0; o >>= 1) q += __shfl_xor_sync(0xffffffffu, q, o);
    __syncthreads();
    if ((d & 31) == 0) red[d >> 5] = q;
    __syncthreads();
    if (d == 0) {
        float t = 0.0f;
        for (int i = 0; i < 8; ++i) t += red[i];
        s_rstd = rsqrtf(t * (1.0f / HID) + 1e-5f);
    }
    __syncthreads();
    const float hv = h[(size_t)n * HID + d] + df * s_rstd * g[d] + b[d];
    if (writeH) h[(size_t)n * HID + d] = hv;
    const __nv_bfloat16 hi = __float2bfloat16(hv);
    const int o = boffA(n, d);
    ah[o] = hi;
    al[o] = __float2bfloat16(hv - __bfloat162float(hi));
}

// ================= neighbor aggregation (emits blocked bf16 split) ============
__global__ void agg_kernel(const float* __restrict__ h, const int* __restrict__ nidx,
                           const float* __restrict__ nw,
                           __nv_bfloat16* __restrict__ gh, __nv_bfloat16* __restrict__ gl) {
    const int n = blockIdx.x;
    const int d = threadIdx.x;
    __shared__ int   sidx[KNB];
    __shared__ float sw  [KNB];
    if (d < KNB) { sidx[d] = nidx[n * KNB + d]; sw[d] = nw[n * KNB + d]; }
    __syncthreads();
    float acc = 0.0f;
#pragma unroll
    for (int k = 0; k < KNB; ++k)
        acc = fmaf(sw[k], h[(size_t)sidx[k] * HID + d], acc);
    const __nv_bfloat16 hi = __float2bfloat16(acc);
    const int o = boffA(n, d);
    gh[o] = hi;
    gl[o] = __float2bfloat16(acc - __bfloat162float(hi));
}

// ================= launch =======================================================
extern "C" void kernel_launch(void* const* d_in, const int* in_sizes, int n_in,
                              void* d_out, int out_size) {
    const float* feats  = (const float*)d_in[0];
    const float* cents  = (const float*)d_in[1];
    const float* enc_w  = (const float*)d_in[2];
    const float* enc_b  = (const float*)d_in[3];
    const float* g1_ws  = (const float*)d_in[4];
    const float* g1_wn  = (const float*)d_in[5];
    const float* g1_g   = (const float*)d_in[6];
    const float* g1_b   = (const float*)d_in[7];
    const float* g2_ws  = (const float*)d_in[8];
    const float* g2_wn  = (const float*)d_in[9];
    const float* g2_g   = (const float*)d_in[10];
    const float* g2_b   = (const float*)d_in[11];
    const float* cls_w1 = (const float*)d_in[12];
    const float* cls_b1 = (const float*)d_in[13];
    const float* cls_w2 = (const float*)d_in[14];
    const float* cls_b2 = (const float*)d_in[15];
    float* out = (float*)d_out;

    float *p_h, *p_tmp, *p_tmp2, *p_nw;
    int* p_nidx;
    __nv_bfloat16 *p_ah, *p_al, *p_gh, *p_gl, *p_wh, *p_wl;
    cudaGetSymbolAddress((void**)&p_h,    g_h);
    cudaGetSymbolAddress((void**)&p_tmp,  g_tmp);
    cudaGetSymbolAddress((void**)&p_tmp2, g_tmp2);
    cudaGetSymbolAddress((void**)&p_nidx, g_nidx);
    cudaGetSymbolAddress((void**)&p_nw,   g_nw);
    cudaGetSymbolAddress((void**)&p_ah,   g_ah);
    cudaGetSymbolAddress((void**)&p_al,   g_al);
    cudaGetSymbolAddress((void**)&p_gh,   g_gh);
    cudaGetSymbolAddress((void**)&p_gl,   g_gl);
    cudaGetSymbolAddress((void**)&p_wh,   g_wh);
    cudaGetSymbolAddress((void**)&p_wl,   g_wl);

    const int M = NPTS;
    const int NBLK = (M + 63) / 64;   // 188
    const int SMEM = 3 * STG_B;       // 73728

    cudaFuncSetAttribute(hmma_gemm_kernel<0, false, true,  false>,
                         cudaFuncAttributeMaxDynamicSharedMemorySize, SMEM);
    cudaFuncSetAttribute(hmma_gemm_kernel<4, false, false, false>,
                         cudaFuncAttributeMaxDynamicSharedMemorySize, SMEM);
    cudaFuncSetAttribute(hmma_gemm_kernel<3, false, false, true >,
                         cudaFuncAttributeMaxDynamicSharedMemorySize, SMEM);
    cudaFuncSetAttribute(hmma_gemm_kernel<3, true,  false, false>,
                         cudaFuncAttributeMaxDynamicSharedMemorySize, SMEM);
    cudaFuncSetAttribute(hmma_gemm_kernel<2, false, false, false>,
                         cudaFuncAttributeMaxDynamicSharedMemorySize, SMEM);

    cudaStream_t s2;
    cudaStreamCreateWithFlags(&s2, cudaStreamNonBlocking);
    cudaEvent_t evF, evJ;
    cudaEventCreateWithFlags(&evF, cudaEventDisableTiming);
    cudaEventCreateWithFlags(&evJ, cudaEventDisableTiming);
    cudaEventRecord(evF, 0);
    cudaStreamWaitEvent(s2, evF, 0);

    const dim3 gFull(NBLK, 2);
    const dim3 gCls(NBLK, 1);

    // ---- s2: KNN (fused build + fast query) ----
    knn_build_kernel<<<1, 1024, 0, s2>>>(cents);
    knn_query_kernel<<<(NPTS * 32 + 255) / 256, 256, 0, s2>>>(p_nidx, p_nw);
    cudaEventRecord(evJ, s2);

    // ---- main: splits -> encoder -> layer1 SELF-GEMM fills the join stall ----
    split_w_kernel<<<(WENC + 255) / 256, 256>>>(
        enc_w, g1_ws, g1_wn, g2_ws, g2_wn, cls_w1, 0, WENC);
    hmma_gemm_kernel<0, false, true, false><<<gFull, 256, SMEM>>>(
        nullptr, nullptr, feats, p_wh + 0, p_wl + 0,
        nullptr, nullptr, nullptr, nullptr,
        enc_b, nullptr, nullptr, nullptr, nullptr,
        p_h, p_ah, p_al, M);
    split_w_kernel<<<(WTOT - WENC + 255) / 256, 256>>>(
        enc_w, g1_ws, g1_wn, g2_ws, g2_wn, cls_w1, WENC, WTOT);
    // layer-1 self half: h @ g1_ws^T -> tmp2 (raw fp32), overlaps knn wait
    hmma_gemm_kernel<4, false, false, false><<<gFull, 256, SMEM>>>(
        p_ah, p_al, nullptr, p_wh + 65536, p_wl + 65536,
        nullptr, nullptr, nullptr, nullptr,
        nullptr, nullptr, nullptr, nullptr, nullptr,
        p_tmp2, nullptr, nullptr, M);

    // join: agg needs knn graph + h
    cudaStreamWaitEvent(0, evJ, 0);

    // ---- SAGE layer 1 (nei half, INITC from tmp2) ----
    agg_kernel<<<NPTS, HID>>>(p_h, p_nidx, p_nw, p_gh, p_gl);
    hmma_gemm_kernel<3, false, false, true><<<gFull, 256, SMEM>>>(
        p_gh, p_gl, nullptr, p_wh + 131072, p_wl + 131072,
        nullptr, nullptr, nullptr, nullptr,
        nullptr, nullptr, nullptr, nullptr, p_tmp2,
        p_tmp, nullptr, nullptr, M);
    ln_res_kernel<<<NPTS, HID>>>(p_tmp, g1_g, g1_b, p_h, p_ah, p_al, 1);

    // ---- SAGE layer 2 (single dual GEMM) ----
    agg_kernel<<<NPTS, HID>>>(p_h, p_nidx, p_nw, p_gh, p_gl);
    hmma_gemm_kernel<3, true, false, false><<<gFull, 256, SMEM>>>(
        p_ah, p_al, nullptr, p_wh + 196608, p_wl + 196608,
        p_gh, p_gl, p_wh + 262144, p_wl + 262144,
        nullptr, nullptr, nullptr, nullptr, nullptr,
        p_tmp, nullptr, nullptr, M);
    ln_res_kernel<<<NPTS, HID>>>(p_tmp, g2_g, g2_b, p_h, p_ah, p_al, 0);

    // ---- classifier (fused dot + sigmoid) ----
    hmma_gemm_kernel<2, false, false, false><<<gCls, 256, SMEM>>>(
        p_ah, p_al, nullptr, p_wh + 327680, p_wl + 327680,
        nullptr, nullptr, nullptr, nullptr,
        cls_b1, cls_w2, cls_b2, out, nullptr,
        nullptr, nullptr, nullptr, M);
}